// round 5
// baseline (speedup 1.0000x reference)
#include <cuda_runtime.h>
#include <cuda_bf16.h>
#include <cstdint>
#include <cstdio>

#define SEQ 2048
#define DIM 4096
#define NH 32
#define NKV 8
#define HD 128
#define KVD (NKV*HD)   // 1024

// Scratch (static __device__ allowed; cudaMalloc is not)
__device__ float g_q[SEQ * DIM];       // 32 MB (tf32-rounded after rope)
__device__ float g_k[SEQ * KVD];       // 8 MB  (tf32-rounded after rope)
__device__ float g_v[SEQ * KVD];       // 8 MB  (tf32-rounded by V-GEMM epilogue)
__device__ float g_attn[SEQ * DIM];    // 32 MB (tf32-rounded + k-permuted)
// Pre-rounded + k-group-permuted copies of GEMM operands
__device__ float g_xr[SEQ * DIM];      // 32 MB
__device__ float g_wqr[DIM * DIM];     // 64 MB
__device__ float g_wkr[KVD * DIM];     // 16 MB
__device__ float g_wvr[KVD * DIM];     // 16 MB
__device__ float g_wor[DIM * DIM];     // 64 MB

__device__ __forceinline__ uint32_t f2tf(float f) {
    uint32_t u;
    asm("cvt.rna.tf32.f32 %0, %1;" : "=r"(u) : "f"(f));
    return u;
}

__device__ __forceinline__ void mma_tf32(float* d,
                                         uint32_t a0, uint32_t a1, uint32_t a2, uint32_t a3,
                                         uint32_t b0, uint32_t b1) {
    asm volatile(
        "mma.sync.aligned.m16n8k8.row.col.f32.tf32.tf32.f32 "
        "{%0,%1,%2,%3}, {%4,%5,%6,%7}, {%8,%9}, {%0,%1,%2,%3};"
        : "+f"(d[0]), "+f"(d[1]), "+f"(d[2]), "+f"(d[3])
        : "r"(a0), "r"(a1), "r"(a2), "r"(a3), "r"(b0), "r"(b1));
}

__device__ __forceinline__ void cp_async16(uint32_t smem_addr, const void* gptr) {
    asm volatile("cp.async.cg.shared.global [%0], [%1], 16;"
                 :: "r"(smem_addr), "l"(gptr) : "memory");
}
#define CP_COMMIT() asm volatile("cp.async.commit_group;" ::: "memory")
#define CP_WAIT(n)  asm volatile("cp.async.wait_group %0;" :: "n"(n) : "memory")

__device__ __forceinline__ uint32_t smem_u32(const void* p) {
    uint32_t a;
    asm("{ .reg .u64 t; cvta.to.shared.u64 t, %1; cvt.u32.u64 %0, t; }" : "=r"(a) : "l"(p));
    return a;
}

// ---------------------------------------------------------------------------
// Prep: round fp32->tf32 AND permute columns within each 8-float k-group:
// dst[p] = round(src[(p>>1) + (p&1)*4]), i.e. src col c lands at (c&3)*2+(c>>2).
// This makes mma fragment k-pairs (k, k+4) adjacent -> LDS.64 in the GEMM.
// ---------------------------------------------------------------------------
__global__ void prep_kernel(const float* __restrict__ src, float* __restrict__ dst, int ngroups) {
    int g = blockIdx.x * blockDim.x + threadIdx.x;
    if (g >= ngroups) return;
    const float4* s = (const float4*)src + (size_t)g * 2;
    float4 lo = s[0], hi = s[1];
    uint4 o0, o1;
    o0.x = f2tf(lo.x); o0.y = f2tf(hi.x); o0.z = f2tf(lo.y); o0.w = f2tf(hi.y);
    o1.x = f2tf(lo.z); o1.y = f2tf(hi.z); o1.z = f2tf(lo.w); o1.w = f2tf(hi.w);
    uint4* d = (uint4*)dst + (size_t)g * 2;
    d[0] = o0; d[1] = o1;
}

// ---------------------------------------------------------------------------
// GEMM: C[M,N] = A[M,K] @ B[N,K]^T. A,B pre-rounded + k-permuted.
// CTA tile 128x256, warp tile 64x64 (2x4 warps), K-chunk 16,
// 3-stage cp.async pipeline, LDS.64 fragment loads (stride 24 floats).
// ---------------------------------------------------------------------------
#define BN 256
#define KC 16
#define GST 24                           // smem row stride (floats)
#define A_STG (128 * GST)                // floats per A stage
#define B_STG (BN  * GST)
#define GEMM_SMEM (3 * (A_STG + B_STG) * 4)   // 110592 B

__global__ void __launch_bounds__(256) gemm_tf32(
    const float* __restrict__ A, const float* __restrict__ B,
    float* __restrict__ C, int N, int K, int round_out)
{
    extern __shared__ float smem[];
    float* As[3]; float* Bs[3];
#pragma unroll
    for (int s = 0; s < 3; s++) {
        As[s] = smem + s * (A_STG + B_STG);
        Bs[s] = As[s] + A_STG;
    }

    const int tid  = threadIdx.x;
    const int warp = tid >> 5, lane = tid & 31;
    const int gid  = lane >> 2, tig = lane & 3;
    const int bm   = blockIdx.y, bn = blockIdx.x;
    const int wm   = warp >> 2, wn = warp & 3;   // 2 x 4 warps, warp tile 64x64

    const float* Ab = A + (size_t)(bm * 128) * K;
    const float* Bb = B + (size_t)(bn * BN) * K;

    // cp.async tile issue for K-chunk kt into stage s
    auto issue = [&](int kt, int s) {
        const float* Ak = Ab + kt * KC;
        const float* Bk = Bb + kt * KC;
        uint32_t as = smem_u32(As[s]);
        uint32_t bs = smem_u32(Bs[s]);
#pragma unroll
        for (int i = 0; i < 2; i++) {            // A: 128 rows x 4 chunks
            int idx = tid + i * 256;
            int r = idx >> 2, c = idx & 3;
            cp_async16(as + (r * GST + c * 4) * 4, Ak + (size_t)r * K + c * 4);
        }
#pragma unroll
        for (int i = 0; i < 4; i++) {            // B: 256 rows x 4 chunks
            int idx = tid + i * 256;
            int r = idx >> 2, c = idx & 3;
            cp_async16(bs + (r * GST + c * 4) * 4, Bk + (size_t)r * K + c * 4);
        }
        CP_COMMIT();
    };

    float acc[4][8][4];
#pragma unroll
    for (int i = 0; i < 4; i++)
#pragma unroll
        for (int j = 0; j < 8; j++)
#pragma unroll
            for (int q = 0; q < 4; q++) acc[i][j][q] = 0.f;

    const int nk = K / KC;
    issue(0, 0);
    issue(1, 1);

    for (int kt = 0; kt < nk; ++kt) {
        if (kt == nk - 1) { CP_WAIT(0); } else { CP_WAIT(1); }
        __syncthreads();
        if (kt + 2 < nk) issue(kt + 2, (kt + 2) % 3);

        const float* as = As[kt % 3];
        const float* bs = Bs[kt % 3];
#pragma unroll
        for (int ks = 0; ks < 2; ++ks) {
            const int kk = ks * 8;
            uint32_t af[4][4], bf[8][2];
#pragma unroll
            for (int mi = 0; mi < 4; ++mi) {
                int r = wm * 64 + mi * 16;
                uint2 p1 = *(const uint2*)&as[(r + gid)     * GST + kk + 2 * tig];
                uint2 p2 = *(const uint2*)&as[(r + gid + 8) * GST + kk + 2 * tig];
                af[mi][0] = p1.x; af[mi][1] = p2.x; af[mi][2] = p1.y; af[mi][3] = p2.y;
            }
#pragma unroll
            for (int ni = 0; ni < 8; ++ni) {
                int c = wn * 64 + ni * 8;
                uint2 q = *(const uint2*)&bs[(c + gid) * GST + kk + 2 * tig];
                bf[ni][0] = q.x; bf[ni][1] = q.y;
            }
#pragma unroll
            for (int mi = 0; mi < 4; ++mi)
#pragma unroll
                for (int ni = 0; ni < 8; ++ni)
                    mma_tf32(acc[mi][ni], af[mi][0], af[mi][1], af[mi][2], af[mi][3],
                             bf[ni][0], bf[ni][1]);
        }
    }

    // epilogue
#pragma unroll
    for (int mi = 0; mi < 4; ++mi) {
        int r0 = bm * 128 + wm * 64 + mi * 16 + gid;
#pragma unroll
        for (int ni = 0; ni < 8; ++ni) {
            int c0 = bn * BN + wn * 64 + ni * 8 + tig * 2;
            if (round_out) {
                uint2 v1, v2;
                v1.x = f2tf(acc[mi][ni][0]); v1.y = f2tf(acc[mi][ni][1]);
                v2.x = f2tf(acc[mi][ni][2]); v2.y = f2tf(acc[mi][ni][3]);
                *(uint2*)&C[(size_t)r0 * N + c0]       = v1;
                *(uint2*)&C[(size_t)(r0 + 8) * N + c0] = v2;
            } else {
                *(float2*)&C[(size_t)r0 * N + c0]       = make_float2(acc[mi][ni][0], acc[mi][ni][1]);
                *(float2*)&C[(size_t)(r0 + 8) * N + c0] = make_float2(acc[mi][ni][2], acc[mi][ni][3]);
            }
        }
    }
}

// ---------------------------------------------------------------------------
// RoPE: fp32 angle math (matches reference's fp32 computation); writes
// tf32-rounded output so attention can load without converting.
// ---------------------------------------------------------------------------
__global__ void rope_kernel(float* __restrict__ t, int H) {
    int idx = blockIdx.x * blockDim.x + threadIdx.x;
    int total = SEQ * H * 64;
    if (idx >= total) return;
    int i  = idx & 63;
    int tp = idx >> 6;
    int hh = tp % H;
    int s  = tp / H;

    float freq = exp2f(-(float)i * (18.931568569324174f / 64.0f));
    float ang = (float)s * freq;
    float sn, cs;
    sincosf(ang, &sn, &cs);

    float* p = t + (size_t)s * (H * HD) + hh * HD + 2 * i;
    float x0 = p[0], x1 = p[1];
    uint2 o;
    o.x = f2tf(x0 * cs - x1 * sn);
    o.y = f2tf(x0 * sn + x1 * cs);
    *(uint2*)p = o;
}

// ---------------------------------------------------------------------------
// Flash attention (causal, GQA group=4), legacy tf32 mma.
// Inputs g_q/g_k/g_v are pre-rounded -> tile loads are plain copies.
// Output written tf32-rounded AND k-group-permuted (feeds O-GEMM A operand).
// ---------------------------------------------------------------------------
#define AS 132
#define ATTN_SMEM (3 * 128 * AS * 4)   // 202752 B

__global__ void __launch_bounds__(256) attn_kernel() {
    extern __shared__ uint32_t sm[];
    uint32_t* Qs = sm;
    uint32_t* Ks = sm + 128 * AS;      // later reused for P
    uint32_t* Vs = sm + 2 * 128 * AS;

    const int qb  = blockIdx.x, h = blockIdx.y;
    const int kvh = h >> 2;
    const int q0  = qb * 128;
    const int tid = threadIdx.x;
    const int warp = tid >> 5, lane = tid & 31;
    const int gid = lane >> 2, tig = lane & 3;
    const int wr  = warp * 16;

    for (int i = tid; i < 128 * 32; i += 256) {
        int r = i >> 5, c = (i & 31) << 2;
        uint4 v = *(const uint4*)(&g_q[(size_t)(q0 + r) * DIM + h * HD + c]);
        *(uint4*)&Qs[r * AS + c] = v;
    }

    float o[16][4];
#pragma unroll
    for (int i = 0; i < 16; i++)
#pragma unroll
        for (int j = 0; j < 4; j++) o[i][j] = 0.f;
    float m1 = -1e30f, m2 = -1e30f, l1 = 0.f, l2 = 0.f;

    for (int kb = 0; kb <= qb; ++kb) {
        __syncthreads();
        for (int i = tid; i < 128 * 32; i += 256) {
            int r = i >> 5, c = (i & 31) << 2;
            uint4 kv = *(const uint4*)(&g_k[(size_t)(kb * 128 + r) * KVD + kvh * HD + c]);
            uint4 vv = *(const uint4*)(&g_v[(size_t)(kb * 128 + r) * KVD + kvh * HD + c]);
            *(uint4*)&Ks[r * AS + c] = kv;
            *(uint4*)&Vs[r * AS + c] = vv;
        }
        __syncthreads();

        float s[16][4];
#pragma unroll
        for (int i = 0; i < 16; i++)
#pragma unroll
            for (int j = 0; j < 4; j++) s[i][j] = 0.f;

#pragma unroll 4
        for (int ks = 0; ks < 16; ++ks) {
            const int kk = ks * 8;
            uint32_t a0 = Qs[(wr + gid)     * AS + kk + tig];
            uint32_t a1 = Qs[(wr + gid + 8) * AS + kk + tig];
            uint32_t a2 = Qs[(wr + gid)     * AS + kk + tig + 4];
            uint32_t a3 = Qs[(wr + gid + 8) * AS + kk + tig + 4];
#pragma unroll
            for (int nt = 0; nt < 16; ++nt) {
                const int n0 = nt * 8;
                uint32_t b0 = Ks[(n0 + gid) * AS + kk + tig];
                uint32_t b1 = Ks[(n0 + gid) * AS + kk + tig + 4];
                mma_tf32(s[nt], a0, a1, a2, a3, b0, b1);
            }
        }
        __syncthreads();

        const float scale = 0.08838834764831845f;  // 1/sqrt(128)
        if (kb == qb) {
            const int r1 = wr + gid, r2 = r1 + 8;
#pragma unroll
            for (int nt = 0; nt < 16; ++nt) {
                int c0 = nt * 8 + tig * 2;
                s[nt][0] = (c0     <= r1) ? s[nt][0] * scale : -1e30f;
                s[nt][1] = (c0 + 1 <= r1) ? s[nt][1] * scale : -1e30f;
                s[nt][2] = (c0     <= r2) ? s[nt][2] * scale : -1e30f;
                s[nt][3] = (c0 + 1 <= r2) ? s[nt][3] * scale : -1e30f;
            }
        } else {
#pragma unroll
            for (int nt = 0; nt < 16; ++nt) {
                s[nt][0] *= scale; s[nt][1] *= scale;
                s[nt][2] *= scale; s[nt][3] *= scale;
            }
        }

        float mx1 = -1e30f, mx2 = -1e30f;
#pragma unroll
        for (int nt = 0; nt < 16; ++nt) {
            mx1 = fmaxf(mx1, fmaxf(s[nt][0], s[nt][1]));
            mx2 = fmaxf(mx2, fmaxf(s[nt][2], s[nt][3]));
        }
        mx1 = fmaxf(mx1, __shfl_xor_sync(0xffffffffu, mx1, 1));
        mx1 = fmaxf(mx1, __shfl_xor_sync(0xffffffffu, mx1, 2));
        mx2 = fmaxf(mx2, __shfl_xor_sync(0xffffffffu, mx2, 1));
        mx2 = fmaxf(mx2, __shfl_xor_sync(0xffffffffu, mx2, 2));

        float nm1 = fmaxf(m1, mx1), nm2 = fmaxf(m2, mx2);
        float al1 = __expf(m1 - nm1), al2 = __expf(m2 - nm2);
        float sum1 = 0.f, sum2 = 0.f;
#pragma unroll
        for (int nt = 0; nt < 16; ++nt) {
            s[nt][0] = __expf(s[nt][0] - nm1); sum1 += s[nt][0];
            s[nt][1] = __expf(s[nt][1] - nm1); sum1 += s[nt][1];
            s[nt][2] = __expf(s[nt][2] - nm2); sum2 += s[nt][2];
            s[nt][3] = __expf(s[nt][3] - nm2); sum2 += s[nt][3];
        }
        sum1 += __shfl_xor_sync(0xffffffffu, sum1, 1);
        sum1 += __shfl_xor_sync(0xffffffffu, sum1, 2);
        sum2 += __shfl_xor_sync(0xffffffffu, sum2, 1);
        sum2 += __shfl_xor_sync(0xffffffffu, sum2, 2);

        l1 = l1 * al1 + sum1; m1 = nm1;
        l2 = l2 * al2 + sum2; m2 = nm2;
#pragma unroll
        for (int nt = 0; nt < 16; ++nt) {
            o[nt][0] *= al1; o[nt][1] *= al1;
            o[nt][2] *= al2; o[nt][3] *= al2;
        }

#pragma unroll
        for (int nt = 0; nt < 16; ++nt) {
            int c0 = nt * 8 + tig * 2;
            uint32_t* p1 = &Ks[(wr + gid) * AS + c0];
            p1[0] = f2tf(s[nt][0]); p1[1] = f2tf(s[nt][1]);
            uint32_t* p2 = &Ks[(wr + gid + 8) * AS + c0];
            p2[0] = f2tf(s[nt][2]); p2[1] = f2tf(s[nt][3]);
        }
        __syncwarp();

#pragma unroll 4
        for (int ks = 0; ks < 16; ++ks) {
            const int kk = ks * 8;
            uint32_t a0 = Ks[(wr + gid)     * AS + kk + tig];
            uint32_t a1 = Ks[(wr + gid + 8) * AS + kk + tig];
            uint32_t a2 = Ks[(wr + gid)     * AS + kk + tig + 4];
            uint32_t a3 = Ks[(wr + gid + 8) * AS + kk + tig + 4];
#pragma unroll
            for (int nt = 0; nt < 16; ++nt) {
                const int n0 = nt * 8;
                uint32_t b0 = Vs[(kk + tig)     * AS + n0 + gid];
                uint32_t b1 = Vs[(kk + tig + 4) * AS + n0 + gid];
                mma_tf32(o[nt], a0, a1, a2, a3, b0, b1);
            }
        }
    }

    // epilogue: tf32-round AND k-group-permute (dst pos of col c: (c&3)*2+(c>>2)).
    // This warp's two cols per nt are c=2*tig and 2*tig+1 within the 8-group:
    //   pos(2t) = {0,4,1,5}[t],  pos(2t+1) = {2,6,3,7}[t]
    const int P0[4] = {0, 4, 1, 5};
    const int P1[4] = {2, 6, 3, 7};
    const float inv1 = 1.f / l1, inv2 = 1.f / l2;
    const int r1 = q0 + wr + gid;
#pragma unroll
    for (int nt = 0; nt < 16; ++nt) {
        size_t base1 = (size_t)r1 * DIM + h * HD + nt * 8;
        size_t base2 = (size_t)(r1 + 8) * DIM + h * HD + nt * 8;
        g_attn[base1 + P0[tig]] = __uint_as_float(f2tf(o[nt][0] * inv1));
        g_attn[base1 + P1[tig]] = __uint_as_float(f2tf(o[nt][1] * inv1));
        g_attn[base2 + P0[tig]] = __uint_as_float(f2tf(o[nt][2] * inv2));
        g_attn[base2 + P1[tig]] = __uint_as_float(f2tf(o[nt][3] * inv2));
    }
}

// ---------------------------------------------------------------------------
extern "C" void kernel_launch(void* const* d_in, const int* in_sizes, int n_in,
                              void* d_out, int out_size) {
    (void)in_sizes; (void)n_in; (void)out_size;
    const float* x  = (const float*)d_in[0];
    const float* wq = (const float*)d_in[1];
    const float* wk = (const float*)d_in[2];
    const float* wv = (const float*)d_in[3];
    const float* wo = (const float*)d_in[4];
    float* out = (float*)d_out;

    float *q, *k, *v, *attn, *xr, *wqr, *wkr, *wvr, *wor;
    cudaGetSymbolAddress((void**)&q, g_q);
    cudaGetSymbolAddress((void**)&k, g_k);
    cudaGetSymbolAddress((void**)&v, g_v);
    cudaGetSymbolAddress((void**)&attn, g_attn);
    cudaGetSymbolAddress((void**)&xr, g_xr);
    cudaGetSymbolAddress((void**)&wqr, g_wqr);
    cudaGetSymbolAddress((void**)&wkr, g_wkr);
    cudaGetSymbolAddress((void**)&wvr, g_wvr);
    cudaGetSymbolAddress((void**)&wor, g_wor);

    cudaFuncSetAttribute(gemm_tf32, cudaFuncAttributeMaxDynamicSharedMemorySize, GEMM_SMEM);
    cudaFuncSetAttribute(attn_kernel, cudaFuncAttributeMaxDynamicSharedMemorySize, ATTN_SMEM);

    // One-time tf32 round + k-group permute of all GEMM operands
    {
        const int T = 256;
        prep_kernel<<<(SEQ * DIM / 8 + T - 1) / T, T>>>(x, xr, SEQ * DIM / 8);
        prep_kernel<<<(DIM * DIM / 8 + T - 1) / T, T>>>(wq, wqr, DIM * DIM / 8);
        prep_kernel<<<(KVD * DIM / 8 + T - 1) / T, T>>>(wk, wkr, KVD * DIM / 8);
        prep_kernel<<<(KVD * DIM / 8 + T - 1) / T, T>>>(wv, wvr, KVD * DIM / 8);
        prep_kernel<<<(DIM * DIM / 8 + T - 1) / T, T>>>(wo, wor, DIM * DIM / 8);
    }

    // Projections
    gemm_tf32<<<dim3(DIM / BN, SEQ / 128), 256, GEMM_SMEM>>>(xr, wqr, q, DIM, DIM, 0);
    gemm_tf32<<<dim3(KVD / BN, SEQ / 128), 256, GEMM_SMEM>>>(xr, wkr, k, KVD, DIM, 0);
    gemm_tf32<<<dim3(KVD / BN, SEQ / 128), 256, GEMM_SMEM>>>(xr, wvr, v, KVD, DIM, 1);

    // RoPE on q and k (writes tf32-rounded)
    rope_kernel<<<(SEQ * NH * 64) / 256, 256>>>(q, NH);
    rope_kernel<<<(SEQ * NKV * 64) / 256, 256>>>(k, NKV);

    // Attention (writes tf32-rounded, k-permuted g_attn)
    attn_kernel<<<dim3(SEQ / 128, NH), 256, ATTN_SMEM>>>();

    // Output projection straight into d_out (full-precision store)
    gemm_tf32<<<dim3(DIM / BN, SEQ / 128), 256, GEMM_SMEM>>>(attn, wor, out, DIM, DIM, 0);
}

// round 6
// speedup vs baseline: 1.2869x; 1.2869x over previous
#include <cuda_runtime.h>
#include <cuda_bf16.h>
#include <cstdint>
#include <cstdio>

#define SEQ 2048
#define DIM 4096
#define NH 32
#define NKV 8
#define HD 128
#define KVD (NKV*HD)   // 1024

// Scratch (static __device__ allowed; cudaMalloc is not)
__device__ float g_q[SEQ * DIM];       // 32 MB (tf32-rounded after rope)
__device__ float g_k[SEQ * KVD];       // 8 MB  (tf32-rounded after rope)
__device__ float g_v[SEQ * KVD];       // 8 MB  (tf32-rounded by V-GEMM epilogue)
__device__ float g_attn[SEQ * DIM];    // 32 MB (tf32-rounded + k-permuted)
// Pre-rounded + k-group-permuted copies of GEMM operands
__device__ float g_xr[SEQ * DIM];      // 32 MB
__device__ float g_wqr[DIM * DIM];     // 64 MB
__device__ float g_wkr[KVD * DIM];     // 16 MB
__device__ float g_wvr[KVD * DIM];     // 16 MB
__device__ float g_wor[DIM * DIM];     // 64 MB

__device__ __forceinline__ uint32_t f2tf(float f) {
    uint32_t u;
    asm("cvt.rna.tf32.f32 %0, %1;" : "=r"(u) : "f"(f));
    return u;
}

__device__ __forceinline__ void mma_tf32(float* d,
                                         uint32_t a0, uint32_t a1, uint32_t a2, uint32_t a3,
                                         uint32_t b0, uint32_t b1) {
    asm volatile(
        "mma.sync.aligned.m16n8k8.row.col.f32.tf32.tf32.f32 "
        "{%0,%1,%2,%3}, {%4,%5,%6,%7}, {%8,%9}, {%0,%1,%2,%3};"
        : "+f"(d[0]), "+f"(d[1]), "+f"(d[2]), "+f"(d[3])
        : "r"(a0), "r"(a1), "r"(a2), "r"(a3), "r"(b0), "r"(b1));
}

__device__ __forceinline__ void cp_async16(uint32_t smem_addr, const void* gptr) {
    asm volatile("cp.async.cg.shared.global [%0], [%1], 16;"
                 :: "r"(smem_addr), "l"(gptr) : "memory");
}
#define CP_COMMIT() asm volatile("cp.async.commit_group;" ::: "memory")
#define CP_WAIT(n)  asm volatile("cp.async.wait_group %0;" :: "n"(n) : "memory")

__device__ __forceinline__ uint32_t smem_u32(const void* p) {
    uint32_t a;
    asm("{ .reg .u64 t; cvta.to.shared.u64 t, %1; cvt.u32.u64 %0, t; }" : "=r"(a) : "l"(p));
    return a;
}

// ---------------------------------------------------------------------------
// Prep: round fp32->tf32 AND permute columns within each 8-float k-group:
// dst[p] = round(src[(p>>1) + (p&1)*4]), i.e. src col c lands at (c&3)*2+(c>>2).
// This makes mma fragment k-pairs (k, k+4) adjacent -> LDS.64 in the GEMM.
// ---------------------------------------------------------------------------
__global__ void prep_kernel(const float* __restrict__ src, float* __restrict__ dst, int ngroups) {
    int g = blockIdx.x * blockDim.x + threadIdx.x;
    if (g >= ngroups) return;
    const float4* s = (const float4*)src + (size_t)g * 2;
    float4 lo = s[0], hi = s[1];
    uint4 o0, o1;
    o0.x = f2tf(lo.x); o0.y = f2tf(hi.x); o0.z = f2tf(lo.y); o0.w = f2tf(hi.y);
    o1.x = f2tf(lo.z); o1.y = f2tf(hi.z); o1.z = f2tf(lo.w); o1.w = f2tf(hi.w);
    uint4* d = (uint4*)dst + (size_t)g * 2;
    d[0] = o0; d[1] = o1;
}

// ---------------------------------------------------------------------------
// GEMM: C[M,N] = A[M,K] @ B[N,K]^T. A,B pre-rounded + k-permuted.
// CTA tile 128x128, warp tile 64x32 (2x4 warps), K-chunk 32,
// 2-stage cp.async double buffer, LDS.64 fragment loads (row stride 40 floats:
// pair-bank = (gid*20 + tig) mod 16 -> conflict-free in both 16-lane phases).
// __launch_bounds__(256,2) pins 2 CTAs/SM (16 warps) for latency cover.
// ---------------------------------------------------------------------------
#define KC 32
#define ST 40                            // smem row stride (floats)
#define A_STG (128 * ST)                 // floats per A stage
#define B_STG (128 * ST)
#define GEMM_SMEM (2 * (A_STG + B_STG) * 4)   // 81920 B

__global__ void __launch_bounds__(256, 2) gemm_tf32(
    const float* __restrict__ A, const float* __restrict__ B,
    float* __restrict__ C, int N, int K, int round_out)
{
    extern __shared__ float smem[];
    float* As[2]; float* Bs[2];
#pragma unroll
    for (int s = 0; s < 2; s++) {
        As[s] = smem + s * (A_STG + B_STG);
        Bs[s] = As[s] + A_STG;
    }

    const int tid  = threadIdx.x;
    const int warp = tid >> 5, lane = tid & 31;
    const int gid  = lane >> 2, tig = lane & 3;
    const int bm   = blockIdx.y, bn = blockIdx.x;
    const int wm   = warp >> 2, wn = warp & 3;   // 2 x 4 warps, warp tile 64x32

    const float* Ab = A + (size_t)(bm * 128) * K;
    const float* Bb = B + (size_t)(bn * 128) * K;

    // cp.async tile issue for K-chunk kt into stage s
    auto issue = [&](int kt, int s) {
        const float* Ak = Ab + kt * KC;
        const float* Bk = Bb + kt * KC;
        uint32_t as = smem_u32(As[s]);
        uint32_t bs = smem_u32(Bs[s]);
#pragma unroll
        for (int i = 0; i < 4; i++) {            // A: 128 rows x 8 float4
            int idx = tid + i * 256;
            int r = idx >> 3, c = idx & 7;
            cp_async16(as + (r * ST + c * 4) * 4, Ak + (size_t)r * K + c * 4);
        }
#pragma unroll
        for (int i = 0; i < 4; i++) {            // B: 128 rows x 8 float4
            int idx = tid + i * 256;
            int r = idx >> 3, c = idx & 7;
            cp_async16(bs + (r * ST + c * 4) * 4, Bk + (size_t)r * K + c * 4);
        }
        CP_COMMIT();
    };

    float acc[4][4][4];
#pragma unroll
    for (int i = 0; i < 4; i++)
#pragma unroll
        for (int j = 0; j < 4; j++)
#pragma unroll
            for (int q = 0; q < 4; q++) acc[i][j][q] = 0.f;

    const int nk = K / KC;
    issue(0, 0);

    for (int kt = 0; kt < nk; ++kt) {
        const int s = kt & 1;
        if (kt + 1 < nk) {
            issue(kt + 1, s ^ 1);
            CP_WAIT(1);
        } else {
            CP_WAIT(0);
        }
        __syncthreads();

        const float* as = As[s];
        const float* bs = Bs[s];
#pragma unroll
        for (int ks = 0; ks < 4; ++ks) {
            const int kk = ks * 8;
            uint32_t af[4][4], bf[4][2];
#pragma unroll
            for (int mi = 0; mi < 4; ++mi) {
                int r = wm * 64 + mi * 16;
                uint2 p1 = *(const uint2*)&as[(r + gid)     * ST + kk + 2 * tig];
                uint2 p2 = *(const uint2*)&as[(r + gid + 8) * ST + kk + 2 * tig];
                af[mi][0] = p1.x; af[mi][1] = p2.x; af[mi][2] = p1.y; af[mi][3] = p2.y;
            }
#pragma unroll
            for (int ni = 0; ni < 4; ++ni) {
                int c = wn * 32 + ni * 8;
                uint2 q = *(const uint2*)&bs[(c + gid) * ST + kk + 2 * tig];
                bf[ni][0] = q.x; bf[ni][1] = q.y;
            }
#pragma unroll
            for (int mi = 0; mi < 4; ++mi)
#pragma unroll
                for (int ni = 0; ni < 4; ++ni)
                    mma_tf32(acc[mi][ni], af[mi][0], af[mi][1], af[mi][2], af[mi][3],
                             bf[ni][0], bf[ni][1]);
        }
        __syncthreads();   // stage s reusable for issue(kt+2)
    }

    // epilogue
#pragma unroll
    for (int mi = 0; mi < 4; ++mi) {
        int r0 = bm * 128 + wm * 64 + mi * 16 + gid;
#pragma unroll
        for (int ni = 0; ni < 4; ++ni) {
            int c0 = bn * 128 + wn * 32 + ni * 8 + tig * 2;
            if (round_out) {
                uint2 v1, v2;
                v1.x = f2tf(acc[mi][ni][0]); v1.y = f2tf(acc[mi][ni][1]);
                v2.x = f2tf(acc[mi][ni][2]); v2.y = f2tf(acc[mi][ni][3]);
                *(uint2*)&C[(size_t)r0 * N + c0]       = v1;
                *(uint2*)&C[(size_t)(r0 + 8) * N + c0] = v2;
            } else {
                *(float2*)&C[(size_t)r0 * N + c0]       = make_float2(acc[mi][ni][0], acc[mi][ni][1]);
                *(float2*)&C[(size_t)(r0 + 8) * N + c0] = make_float2(acc[mi][ni][2], acc[mi][ni][3]);
            }
        }
    }
}

// ---------------------------------------------------------------------------
// RoPE: fp32 angle math (matches reference's fp32 computation); writes
// tf32-rounded output so attention can load without converting.
// ---------------------------------------------------------------------------
__global__ void rope_kernel(float* __restrict__ t, int H) {
    int idx = blockIdx.x * blockDim.x + threadIdx.x;
    int total = SEQ * H * 64;
    if (idx >= total) return;
    int i  = idx & 63;
    int tp = idx >> 6;
    int hh = tp % H;
    int s  = tp / H;

    float freq = exp2f(-(float)i * (18.931568569324174f / 64.0f));
    float ang = (float)s * freq;
    float sn, cs;
    sincosf(ang, &sn, &cs);

    float* p = t + (size_t)s * (H * HD) + hh * HD + 2 * i;
    float x0 = p[0], x1 = p[1];
    uint2 o;
    o.x = f2tf(x0 * cs - x1 * sn);
    o.y = f2tf(x0 * sn + x1 * cs);
    *(uint2*)p = o;
}

// ---------------------------------------------------------------------------
// Flash attention (causal, GQA group=4), legacy tf32 mma.
// Inputs g_q/g_k/g_v are pre-rounded -> tile loads are plain copies.
// Output written tf32-rounded AND k-group-permuted (feeds O-GEMM A operand).
// ---------------------------------------------------------------------------
#define AS 132
#define ATTN_SMEM (3 * 128 * AS * 4)   // 202752 B

__global__ void __launch_bounds__(256) attn_kernel() {
    extern __shared__ uint32_t sm[];
    uint32_t* Qs = sm;
    uint32_t* Ks = sm + 128 * AS;      // later reused for P
    uint32_t* Vs = sm + 2 * 128 * AS;

    const int qb  = blockIdx.x, h = blockIdx.y;
    const int kvh = h >> 2;
    const int q0  = qb * 128;
    const int tid = threadIdx.x;
    const int warp = tid >> 5, lane = tid & 31;
    const int gid = lane >> 2, tig = lane & 3;
    const int wr  = warp * 16;

    for (int i = tid; i < 128 * 32; i += 256) {
        int r = i >> 5, c = (i & 31) << 2;
        uint4 v = *(const uint4*)(&g_q[(size_t)(q0 + r) * DIM + h * HD + c]);
        *(uint4*)&Qs[r * AS + c] = v;
    }

    float o[16][4];
#pragma unroll
    for (int i = 0; i < 16; i++)
#pragma unroll
        for (int j = 0; j < 4; j++) o[i][j] = 0.f;
    float m1 = -1e30f, m2 = -1e30f, l1 = 0.f, l2 = 0.f;

    for (int kb = 0; kb <= qb; ++kb) {
        __syncthreads();
        for (int i = tid; i < 128 * 32; i += 256) {
            int r = i >> 5, c = (i & 31) << 2;
            uint4 kv = *(const uint4*)(&g_k[(size_t)(kb * 128 + r) * KVD + kvh * HD + c]);
            uint4 vv = *(const uint4*)(&g_v[(size_t)(kb * 128 + r) * KVD + kvh * HD + c]);
            *(uint4*)&Ks[r * AS + c] = kv;
            *(uint4*)&Vs[r * AS + c] = vv;
        }
        __syncthreads();

        float s[16][4];
#pragma unroll
        for (int i = 0; i < 16; i++)
#pragma unroll
            for (int j = 0; j < 4; j++) s[i][j] = 0.f;

#pragma unroll 4
        for (int ks = 0; ks < 16; ++ks) {
            const int kk = ks * 8;
            uint32_t a0 = Qs[(wr + gid)     * AS + kk + tig];
            uint32_t a1 = Qs[(wr + gid + 8) * AS + kk + tig];
            uint32_t a2 = Qs[(wr + gid)     * AS + kk + tig + 4];
            uint32_t a3 = Qs[(wr + gid + 8) * AS + kk + tig + 4];
#pragma unroll
            for (int nt = 0; nt < 16; ++nt) {
                const int n0 = nt * 8;
                uint32_t b0 = Ks[(n0 + gid) * AS + kk + tig];
                uint32_t b1 = Ks[(n0 + gid) * AS + kk + tig + 4];
                mma_tf32(s[nt], a0, a1, a2, a3, b0, b1);
            }
        }
        __syncthreads();

        const float scale = 0.08838834764831845f;  // 1/sqrt(128)
        if (kb == qb) {
            const int r1 = wr + gid, r2 = r1 + 8;
#pragma unroll
            for (int nt = 0; nt < 16; ++nt) {
                int c0 = nt * 8 + tig * 2;
                s[nt][0] = (c0     <= r1) ? s[nt][0] * scale : -1e30f;
                s[nt][1] = (c0 + 1 <= r1) ? s[nt][1] * scale : -1e30f;
                s[nt][2] = (c0     <= r2) ? s[nt][2] * scale : -1e30f;
                s[nt][3] = (c0 + 1 <= r2) ? s[nt][3] * scale : -1e30f;
            }
        } else {
#pragma unroll
            for (int nt = 0; nt < 16; ++nt) {
                s[nt][0] *= scale; s[nt][1] *= scale;
                s[nt][2] *= scale; s[nt][3] *= scale;
            }
        }

        float mx1 = -1e30f, mx2 = -1e30f;
#pragma unroll
        for (int nt = 0; nt < 16; ++nt) {
            mx1 = fmaxf(mx1, fmaxf(s[nt][0], s[nt][1]));
            mx2 = fmaxf(mx2, fmaxf(s[nt][2], s[nt][3]));
        }
        mx1 = fmaxf(mx1, __shfl_xor_sync(0xffffffffu, mx1, 1));
        mx1 = fmaxf(mx1, __shfl_xor_sync(0xffffffffu, mx1, 2));
        mx2 = fmaxf(mx2, __shfl_xor_sync(0xffffffffu, mx2, 1));
        mx2 = fmaxf(mx2, __shfl_xor_sync(0xffffffffu, mx2, 2));

        float nm1 = fmaxf(m1, mx1), nm2 = fmaxf(m2, mx2);
        float al1 = __expf(m1 - nm1), al2 = __expf(m2 - nm2);
        float sum1 = 0.f, sum2 = 0.f;
#pragma unroll
        for (int nt = 0; nt < 16; ++nt) {
            s[nt][0] = __expf(s[nt][0] - nm1); sum1 += s[nt][0];
            s[nt][1] = __expf(s[nt][1] - nm1); sum1 += s[nt][1];
            s[nt][2] = __expf(s[nt][2] - nm2); sum2 += s[nt][2];
            s[nt][3] = __expf(s[nt][3] - nm2); sum2 += s[nt][3];
        }
        sum1 += __shfl_xor_sync(0xffffffffu, sum1, 1);
        sum1 += __shfl_xor_sync(0xffffffffu, sum1, 2);
        sum2 += __shfl_xor_sync(0xffffffffu, sum2, 1);
        sum2 += __shfl_xor_sync(0xffffffffu, sum2, 2);

        l1 = l1 * al1 + sum1; m1 = nm1;
        l2 = l2 * al2 + sum2; m2 = nm2;
#pragma unroll
        for (int nt = 0; nt < 16; ++nt) {
            o[nt][0] *= al1; o[nt][1] *= al1;
            o[nt][2] *= al2; o[nt][3] *= al2;
        }

#pragma unroll
        for (int nt = 0; nt < 16; ++nt) {
            int c0 = nt * 8 + tig * 2;
            uint32_t* p1 = &Ks[(wr + gid) * AS + c0];
            p1[0] = f2tf(s[nt][0]); p1[1] = f2tf(s[nt][1]);
            uint32_t* p2 = &Ks[(wr + gid + 8) * AS + c0];
            p2[0] = f2tf(s[nt][2]); p2[1] = f2tf(s[nt][3]);
        }
        __syncwarp();

#pragma unroll 4
        for (int ks = 0; ks < 16; ++ks) {
            const int kk = ks * 8;
            uint32_t a0 = Ks[(wr + gid)     * AS + kk + tig];
            uint32_t a1 = Ks[(wr + gid + 8) * AS + kk + tig];
            uint32_t a2 = Ks[(wr + gid)     * AS + kk + tig + 4];
            uint32_t a3 = Ks[(wr + gid + 8) * AS + kk + tig + 4];
#pragma unroll
            for (int nt = 0; nt < 16; ++nt) {
                const int n0 = nt * 8;
                uint32_t b0 = Vs[(kk + tig)     * AS + n0 + gid];
                uint32_t b1 = Vs[(kk + tig + 4) * AS + n0 + gid];
                mma_tf32(o[nt], a0, a1, a2, a3, b0, b1);
            }
        }
    }

    // epilogue: tf32-round AND k-group-permute (dst pos of col c: (c&3)*2+(c>>2)).
    const int P0[4] = {0, 4, 1, 5};
    const int P1[4] = {2, 6, 3, 7};
    const float inv1 = 1.f / l1, inv2 = 1.f / l2;
    const int r1 = q0 + wr + gid;
#pragma unroll
    for (int nt = 0; nt < 16; ++nt) {
        size_t base1 = (size_t)r1 * DIM + h * HD + nt * 8;
        size_t base2 = (size_t)(r1 + 8) * DIM + h * HD + nt * 8;
        g_attn[base1 + P0[tig]] = __uint_as_float(f2tf(o[nt][0] * inv1));
        g_attn[base1 + P1[tig]] = __uint_as_float(f2tf(o[nt][1] * inv1));
        g_attn[base2 + P0[tig]] = __uint_as_float(f2tf(o[nt][2] * inv2));
        g_attn[base2 + P1[tig]] = __uint_as_float(f2tf(o[nt][3] * inv2));
    }
}

// ---------------------------------------------------------------------------
extern "C" void kernel_launch(void* const* d_in, const int* in_sizes, int n_in,
                              void* d_out, int out_size) {
    (void)in_sizes; (void)n_in; (void)out_size;
    const float* x  = (const float*)d_in[0];
    const float* wq = (const float*)d_in[1];
    const float* wk = (const float*)d_in[2];
    const float* wv = (const float*)d_in[3];
    const float* wo = (const float*)d_in[4];
    float* out = (float*)d_out;

    float *q, *k, *v, *attn, *xr, *wqr, *wkr, *wvr, *wor;
    cudaGetSymbolAddress((void**)&q, g_q);
    cudaGetSymbolAddress((void**)&k, g_k);
    cudaGetSymbolAddress((void**)&v, g_v);
    cudaGetSymbolAddress((void**)&attn, g_attn);
    cudaGetSymbolAddress((void**)&xr, g_xr);
    cudaGetSymbolAddress((void**)&wqr, g_wqr);
    cudaGetSymbolAddress((void**)&wkr, g_wkr);
    cudaGetSymbolAddress((void**)&wvr, g_wvr);
    cudaGetSymbolAddress((void**)&wor, g_wor);

    cudaFuncSetAttribute(gemm_tf32, cudaFuncAttributeMaxDynamicSharedMemorySize, GEMM_SMEM);
    cudaFuncSetAttribute(attn_kernel, cudaFuncAttributeMaxDynamicSharedMemorySize, ATTN_SMEM);

    // One-time tf32 round + k-group permute of all GEMM operands
    {
        const int T = 256;
        prep_kernel<<<(SEQ * DIM / 8 + T - 1) / T, T>>>(x, xr, SEQ * DIM / 8);
        prep_kernel<<<(DIM * DIM / 8 + T - 1) / T, T>>>(wq, wqr, DIM * DIM / 8);
        prep_kernel<<<(KVD * DIM / 8 + T - 1) / T, T>>>(wk, wkr, KVD * DIM / 8);
        prep_kernel<<<(KVD * DIM / 8 + T - 1) / T, T>>>(wv, wvr, KVD * DIM / 8);
        prep_kernel<<<(DIM * DIM / 8 + T - 1) / T, T>>>(wo, wor, DIM * DIM / 8);
    }

    // Projections
    gemm_tf32<<<dim3(DIM / 128, SEQ / 128), 256, GEMM_SMEM>>>(xr, wqr, q, DIM, DIM, 0);
    gemm_tf32<<<dim3(KVD / 128, SEQ / 128), 256, GEMM_SMEM>>>(xr, wkr, k, KVD, DIM, 0);
    gemm_tf32<<<dim3(KVD / 128, SEQ / 128), 256, GEMM_SMEM>>>(xr, wvr, v, KVD, DIM, 1);

    // RoPE on q and k (writes tf32-rounded)
    rope_kernel<<<(SEQ * NH * 64) / 256, 256>>>(q, NH);
    rope_kernel<<<(SEQ * NKV * 64) / 256, 256>>>(k, NKV);

    // Attention (writes tf32-rounded, k-permuted g_attn)
    attn_kernel<<<dim3(SEQ / 128, NH), 256, ATTN_SMEM>>>();

    // Output projection straight into d_out (full-precision store)
    gemm_tf32<<<dim3(DIM / 128, SEQ / 128), 256, GEMM_SMEM>>>(attn, wor, out, DIM, DIM, 0);
}

// round 7
// speedup vs baseline: 1.5305x; 1.1893x over previous
#include <cuda_runtime.h>
#include <cuda_bf16.h>
#include <cstdint>
#include <cstdio>

#define SEQ 2048
#define DIM 4096
#define NH 32
#define NKV 8
#define HD 128
#define KVD (NKV*HD)   // 1024

__device__ float g_q[SEQ * DIM];       // 32 MB (tf32-rounded after rope)
__device__ float g_k[SEQ * KVD];       // 8 MB  (tf32-rounded after rope)
__device__ float g_v[SEQ * KVD];       // 8 MB  (tf32-rounded by V epilogue)
__device__ float g_attn[SEQ * DIM];    // 32 MB (tf32-rounded + k-permuted)
__device__ float g_xr[SEQ * DIM];      // 32 MB
__device__ float g_wqr[DIM * DIM];     // 64 MB
__device__ float g_wkr[KVD * DIM];     // 16 MB
__device__ float g_wvr[KVD * DIM];     // 16 MB
__device__ float g_wor[DIM * DIM];     // 64 MB

__device__ __forceinline__ uint32_t f2tf(float f) {
    uint32_t u;
    asm("cvt.rna.tf32.f32 %0, %1;" : "=r"(u) : "f"(f));
    return u;
}

__device__ __forceinline__ void mma_tf32(float* d,
                                         uint32_t a0, uint32_t a1, uint32_t a2, uint32_t a3,
                                         uint32_t b0, uint32_t b1) {
    asm volatile(
        "mma.sync.aligned.m16n8k8.row.col.f32.tf32.tf32.f32 "
        "{%0,%1,%2,%3}, {%4,%5,%6,%7}, {%8,%9}, {%0,%1,%2,%3};"
        : "+f"(d[0]), "+f"(d[1]), "+f"(d[2]), "+f"(d[3])
        : "r"(a0), "r"(a1), "r"(a2), "r"(a3), "r"(b0), "r"(b1));
}

__device__ __forceinline__ void cp_async16(uint32_t smem_addr, const void* gptr) {
    asm volatile("cp.async.cg.shared.global [%0], [%1], 16;"
                 :: "r"(smem_addr), "l"(gptr) : "memory");
}
#define CP_COMMIT() asm volatile("cp.async.commit_group;" ::: "memory")
#define CP_WAIT(n)  asm volatile("cp.async.wait_group %0;" :: "n"(n) : "memory")

__device__ __forceinline__ uint32_t smem_u32(const void* p) {
    uint32_t a;
    asm("{ .reg .u64 t; cvta.to.shared.u64 t, %1; cvt.u32.u64 %0, t; }" : "=r"(a) : "l"(p));
    return a;
}

// ---------------------------------------------------------------------------
// Prep: round fp32->tf32 AND permute columns within each 8-float k-group:
// src col c lands at (c&3)*2 + (c>>2)  ->  LDS.64 fragment pairs in GEMMs.
// ---------------------------------------------------------------------------
__global__ void prep_kernel(const float* __restrict__ src, float* __restrict__ dst, int ngroups) {
    int g = blockIdx.x * blockDim.x + threadIdx.x;
    if (g >= ngroups) return;
    const float4* s = (const float4*)src + (size_t)g * 2;
    float4 lo = s[0], hi = s[1];
    uint4 o0, o1;
    o0.x = f2tf(lo.x); o0.y = f2tf(hi.x); o0.z = f2tf(lo.y); o0.w = f2tf(hi.y);
    o1.x = f2tf(lo.z); o1.y = f2tf(hi.z); o1.z = f2tf(lo.w); o1.w = f2tf(hi.w);
    uint4* d = (uint4*)dst + (size_t)g * 2;
    d[0] = o0; d[1] = o1;
}

// ---------------------------------------------------------------------------
// GEMM core: C[M,N] = A[M,K] @ B[N,K]^T (pre-rounded + k-permuted operands).
// CTA tile 128x128, 4 warps of 64x64 (2x2), K-chunk 32, 2-stage cp.async,
// LDS.64 fragments at row stride 40 (conflict-free), 2 CTAs/SM.
// ---------------------------------------------------------------------------
#define KC 32
#define ST 40
#define A_STG (128 * ST)
#define B_STG (128 * ST)
#define GEMM_SMEM (2 * (A_STG + B_STG) * 4)   // 81920 B

__device__ __forceinline__ void gemm_body(
    const float* __restrict__ A, const float* __restrict__ B,
    float* __restrict__ C, int N, int K, int round_out,
    int bm, int bn, float* smem)
{
    float* As[2]; float* Bs[2];
#pragma unroll
    for (int s = 0; s < 2; s++) {
        As[s] = smem + s * (A_STG + B_STG);
        Bs[s] = As[s] + A_STG;
    }

    const int tid  = threadIdx.x;
    const int warp = tid >> 5, lane = tid & 31;
    const int gid  = lane >> 2, tig = lane & 3;
    const int wm   = warp >> 1, wn = warp & 1;   // 2x2 warps, warp tile 64x64

    const float* Ab = A + (size_t)(bm * 128) * K;
    const float* Bb = B + (size_t)(bn * 128) * K;

    auto issue = [&](int kt, int s) {
        const float* Ak = Ab + kt * KC;
        const float* Bk = Bb + kt * KC;
        uint32_t as = smem_u32(As[s]);
        uint32_t bs = smem_u32(Bs[s]);
#pragma unroll
        for (int i = 0; i < 8; i++) {            // A: 128 rows x 8 x 16B
            int idx = tid + i * 128;
            int r = idx >> 3, c = idx & 7;
            cp_async16(as + (r * ST + c * 4) * 4, Ak + (size_t)r * K + c * 4);
        }
#pragma unroll
        for (int i = 0; i < 8; i++) {            // B: 128 rows x 8 x 16B
            int idx = tid + i * 128;
            int r = idx >> 3, c = idx & 7;
            cp_async16(bs + (r * ST + c * 4) * 4, Bk + (size_t)r * K + c * 4);
        }
        CP_COMMIT();
    };

    float acc[4][8][4];
#pragma unroll
    for (int i = 0; i < 4; i++)
#pragma unroll
        for (int j = 0; j < 8; j++)
#pragma unroll
            for (int q = 0; q < 4; q++) acc[i][j][q] = 0.f;

    const int nk = K / KC;
    issue(0, 0);

    for (int kt = 0; kt < nk; ++kt) {
        const int s = kt & 1;
        if (kt + 1 < nk) {
            issue(kt + 1, s ^ 1);
            CP_WAIT(1);
        } else {
            CP_WAIT(0);
        }
        __syncthreads();

        const float* as = As[s];
        const float* bs = Bs[s];
#pragma unroll
        for (int ks = 0; ks < 4; ++ks) {
            const int kk = ks * 8;
            uint32_t af[4][4], bf[8][2];
#pragma unroll
            for (int mi = 0; mi < 4; ++mi) {
                int r = wm * 64 + mi * 16;
                uint2 p1 = *(const uint2*)&as[(r + gid)     * ST + kk + 2 * tig];
                uint2 p2 = *(const uint2*)&as[(r + gid + 8) * ST + kk + 2 * tig];
                af[mi][0] = p1.x; af[mi][1] = p2.x; af[mi][2] = p1.y; af[mi][3] = p2.y;
            }
#pragma unroll
            for (int ni = 0; ni < 8; ++ni) {
                int c = wn * 64 + ni * 8;
                uint2 q = *(const uint2*)&bs[(c + gid) * ST + kk + 2 * tig];
                bf[ni][0] = q.x; bf[ni][1] = q.y;
            }
#pragma unroll
            for (int mi = 0; mi < 4; ++mi)
#pragma unroll
                for (int ni = 0; ni < 8; ++ni)
                    mma_tf32(acc[mi][ni], af[mi][0], af[mi][1], af[mi][2], af[mi][3],
                             bf[ni][0], bf[ni][1]);
        }
        __syncthreads();
    }

#pragma unroll
    for (int mi = 0; mi < 4; ++mi) {
        int r0 = bm * 128 + wm * 64 + mi * 16 + gid;
#pragma unroll
        for (int ni = 0; ni < 8; ++ni) {
            int c0 = bn * 128 + wn * 64 + ni * 8 + tig * 2;
            if (round_out) {
                uint2 v1, v2;
                v1.x = f2tf(acc[mi][ni][0]); v1.y = f2tf(acc[mi][ni][1]);
                v2.x = f2tf(acc[mi][ni][2]); v2.y = f2tf(acc[mi][ni][3]);
                *(uint2*)&C[(size_t)r0 * N + c0]       = v1;
                *(uint2*)&C[(size_t)(r0 + 8) * N + c0] = v2;
            } else {
                *(float2*)&C[(size_t)r0 * N + c0]       = make_float2(acc[mi][ni][0], acc[mi][ni][1]);
                *(float2*)&C[(size_t)(r0 + 8) * N + c0] = make_float2(acc[mi][ni][2], acc[mi][ni][3]);
            }
        }
    }
}

// Merged Q/K/V projection: grid.x = 48 column tiles (q:0-31, k:32-39, v:40-47)
__global__ void __launch_bounds__(128, 2) gemm_qkv_kernel() {
    extern __shared__ float smem[];
    int bx = blockIdx.x, bm = blockIdx.y;
    const float* B; float* C; int N, bn, ro;
    if (bx < 32)      { B = g_wqr; C = g_q; N = DIM; bn = bx;      ro = 0; }
    else if (bx < 40) { B = g_wkr; C = g_k; N = KVD; bn = bx - 32; ro = 0; }
    else              { B = g_wvr; C = g_v; N = KVD; bn = bx - 40; ro = 1; }
    gemm_body(g_xr, B, C, N, DIM, ro, bm, bn, smem);
}

// Plain GEMM (used for O-projection)
__global__ void __launch_bounds__(128, 2) gemm_kernel(
    const float* __restrict__ A, const float* __restrict__ B,
    float* __restrict__ C, int N, int K, int round_out)
{
    extern __shared__ float smem[];
    gemm_body(A, B, C, N, K, round_out, blockIdx.y, blockIdx.x, smem);
}

// ---------------------------------------------------------------------------
// RoPE: fp32 angle math; writes tf32-rounded output.
// ---------------------------------------------------------------------------
__global__ void rope_kernel(float* __restrict__ t, int H) {
    int idx = blockIdx.x * blockDim.x + threadIdx.x;
    int total = SEQ * H * 64;
    if (idx >= total) return;
    int i  = idx & 63;
    int tp = idx >> 6;
    int hh = tp % H;
    int s  = tp / H;

    float freq = exp2f(-(float)i * (18.931568569324174f / 64.0f));
    float ang = (float)s * freq;
    float sn, cs;
    sincosf(ang, &sn, &cs);

    float* p = t + (size_t)s * (H * HD) + hh * HD + 2 * i;
    float x0 = p[0], x1 = p[1];
    uint2 o;
    o.x = f2tf(x0 * cs - x1 * sn);
    o.y = f2tf(x0 * sn + x1 * cs);
    *(uint2*)p = o;
}

// ---------------------------------------------------------------------------
// Flash attention v2 (causal, GQA group=4), legacy tf32 mma.
// CTA = 64 q-rows x one head; KV blocks of 64; 128 threads (4 warps x 16 rows).
// smem 99 KB -> 2 CTAs/SM. Longest-tile-first via qt remap.
// Output tf32-rounded + k-permuted (A operand of O-projection).
// ---------------------------------------------------------------------------
#define AS2 132
#define ATTN_SMEM (3 * 64 * AS2 * 4)   // 101376 B

__global__ void __launch_bounds__(128, 2) attn_kernel() {
    extern __shared__ uint32_t sm[];
    uint32_t* Qs = sm;                  // 64 x AS2
    uint32_t* Ks = sm + 64 * AS2;       // 64 x AS2 (reused as P)
    uint32_t* Vs = sm + 2 * 64 * AS2;   // 64 x AS2

    const int qt  = (int)(gridDim.x - 1) - (int)blockIdx.x;  // longest first
    const int h   = blockIdx.y;
    const int kvh = h >> 2;
    const int q0  = qt * 64;
    const int tid = threadIdx.x;
    const int warp = tid >> 5, lane = tid & 31;
    const int gid = lane >> 2, tig = lane & 3;
    const int wr  = warp * 16;

    // Q tile 64 x 128 (already tf32-rounded)
    for (int i = tid; i < 64 * 32; i += 128) {
        int r = i >> 5, c = (i & 31) << 2;
        uint4 v = *(const uint4*)(&g_q[(size_t)(q0 + r) * DIM + h * HD + c]);
        *(uint4*)&Qs[r * AS2 + c] = v;
    }

    float o[16][4];
#pragma unroll
    for (int i = 0; i < 16; i++)
#pragma unroll
        for (int j = 0; j < 4; j++) o[i][j] = 0.f;
    float m1 = -1e30f, m2 = -1e30f, l1 = 0.f, l2 = 0.f;

    for (int kb = 0; kb <= qt; ++kb) {
        __syncthreads();  // previous P/V consumers done
        for (int i = tid; i < 64 * 32; i += 128) {
            int r = i >> 5, c = (i & 31) << 2;
            uint4 kv = *(const uint4*)(&g_k[(size_t)(kb * 64 + r) * KVD + kvh * HD + c]);
            uint4 vv = *(const uint4*)(&g_v[(size_t)(kb * 64 + r) * KVD + kvh * HD + c]);
            *(uint4*)&Ks[r * AS2 + c] = kv;
            *(uint4*)&Vs[r * AS2 + c] = vv;
        }
        __syncthreads();

        // scores: 16 q rows x 64 kv cols, K-dim = 128 (head dim)
        float s[8][4];
#pragma unroll
        for (int i = 0; i < 8; i++)
#pragma unroll
            for (int j = 0; j < 4; j++) s[i][j] = 0.f;

#pragma unroll 4
        for (int ks = 0; ks < 16; ++ks) {
            const int kk = ks * 8;
            uint32_t a0 = Qs[(wr + gid)     * AS2 + kk + tig];
            uint32_t a1 = Qs[(wr + gid + 8) * AS2 + kk + tig];
            uint32_t a2 = Qs[(wr + gid)     * AS2 + kk + tig + 4];
            uint32_t a3 = Qs[(wr + gid + 8) * AS2 + kk + tig + 4];
#pragma unroll
            for (int nt = 0; nt < 8; ++nt) {
                const int n0 = nt * 8;
                uint32_t b0 = Ks[(n0 + gid) * AS2 + kk + tig];
                uint32_t b1 = Ks[(n0 + gid) * AS2 + kk + tig + 4];
                mma_tf32(s[nt], a0, a1, a2, a3, b0, b1);
            }
        }
        __syncthreads();  // all Ks reads done before P overwrite

        const float scale = 0.08838834764831845f;  // 1/sqrt(128)
        if (kb == qt) {   // diagonal block: local col vs local row
            const int r1 = wr + gid, r2 = r1 + 8;
#pragma unroll
            for (int nt = 0; nt < 8; ++nt) {
                int c0 = nt * 8 + tig * 2;
                s[nt][0] = (c0     <= r1) ? s[nt][0] * scale : -1e30f;
                s[nt][1] = (c0 + 1 <= r1) ? s[nt][1] * scale : -1e30f;
                s[nt][2] = (c0     <= r2) ? s[nt][2] * scale : -1e30f;
                s[nt][3] = (c0 + 1 <= r2) ? s[nt][3] * scale : -1e30f;
            }
        } else {
#pragma unroll
            for (int nt = 0; nt < 8; ++nt) {
                s[nt][0] *= scale; s[nt][1] *= scale;
                s[nt][2] *= scale; s[nt][3] *= scale;
            }
        }

        float mx1 = -1e30f, mx2 = -1e30f;
#pragma unroll
        for (int nt = 0; nt < 8; ++nt) {
            mx1 = fmaxf(mx1, fmaxf(s[nt][0], s[nt][1]));
            mx2 = fmaxf(mx2, fmaxf(s[nt][2], s[nt][3]));
        }
        mx1 = fmaxf(mx1, __shfl_xor_sync(0xffffffffu, mx1, 1));
        mx1 = fmaxf(mx1, __shfl_xor_sync(0xffffffffu, mx1, 2));
        mx2 = fmaxf(mx2, __shfl_xor_sync(0xffffffffu, mx2, 1));
        mx2 = fmaxf(mx2, __shfl_xor_sync(0xffffffffu, mx2, 2));

        float nm1 = fmaxf(m1, mx1), nm2 = fmaxf(m2, mx2);
        float al1 = __expf(m1 - nm1), al2 = __expf(m2 - nm2);
        float sum1 = 0.f, sum2 = 0.f;
#pragma unroll
        for (int nt = 0; nt < 8; ++nt) {
            s[nt][0] = __expf(s[nt][0] - nm1); sum1 += s[nt][0];
            s[nt][1] = __expf(s[nt][1] - nm1); sum1 += s[nt][1];
            s[nt][2] = __expf(s[nt][2] - nm2); sum2 += s[nt][2];
            s[nt][3] = __expf(s[nt][3] - nm2); sum2 += s[nt][3];
        }
        sum1 += __shfl_xor_sync(0xffffffffu, sum1, 1);
        sum1 += __shfl_xor_sync(0xffffffffu, sum1, 2);
        sum2 += __shfl_xor_sync(0xffffffffu, sum2, 1);
        sum2 += __shfl_xor_sync(0xffffffffu, sum2, 2);

        l1 = l1 * al1 + sum1; m1 = nm1;
        l2 = l2 * al2 + sum2; m2 = nm2;
#pragma unroll
        for (int nt = 0; nt < 16; ++nt) {
            o[nt][0] *= al1; o[nt][1] *= al1;
            o[nt][2] *= al2; o[nt][3] *= al2;
        }

        // write P (tf32) into Ks — each warp its own 16 rows
#pragma unroll
        for (int nt = 0; nt < 8; ++nt) {
            int c0 = nt * 8 + tig * 2;
            uint32_t* p1 = &Ks[(wr + gid) * AS2 + c0];
            p1[0] = f2tf(s[nt][0]); p1[1] = f2tf(s[nt][1]);
            uint32_t* p2 = &Ks[(wr + gid + 8) * AS2 + c0];
            p2[0] = f2tf(s[nt][2]); p2[1] = f2tf(s[nt][3]);
        }
        __syncwarp();

        // o += P @ V   (K-dim = 64 kv positions, 128 head cols)
#pragma unroll 4
        for (int ks = 0; ks < 8; ++ks) {
            const int kk = ks * 8;
            uint32_t a0 = Ks[(wr + gid)     * AS2 + kk + tig];
            uint32_t a1 = Ks[(wr + gid + 8) * AS2 + kk + tig];
            uint32_t a2 = Ks[(wr + gid)     * AS2 + kk + tig + 4];
            uint32_t a3 = Ks[(wr + gid + 8) * AS2 + kk + tig + 4];
#pragma unroll
            for (int nt = 0; nt < 16; ++nt) {
                const int n0 = nt * 8;
                uint32_t b0 = Vs[(kk + tig)     * AS2 + n0 + gid];
                uint32_t b1 = Vs[(kk + tig + 4) * AS2 + n0 + gid];
                mma_tf32(o[nt], a0, a1, a2, a3, b0, b1);
            }
        }
    }

    // epilogue: tf32-round AND k-group-permute for the O-GEMM A operand.
    const int P0[4] = {0, 4, 1, 5};
    const int P1[4] = {2, 6, 3, 7};
    const float inv1 = 1.f / l1, inv2 = 1.f / l2;
    const int r1 = q0 + wr + gid;
#pragma unroll
    for (int nt = 0; nt < 16; ++nt) {
        size_t base1 = (size_t)r1 * DIM + h * HD + nt * 8;
        size_t base2 = (size_t)(r1 + 8) * DIM + h * HD + nt * 8;
        g_attn[base1 + P0[tig]] = __uint_as_float(f2tf(o[nt][0] * inv1));
        g_attn[base1 + P1[tig]] = __uint_as_float(f2tf(o[nt][1] * inv1));
        g_attn[base2 + P0[tig]] = __uint_as_float(f2tf(o[nt][2] * inv2));
        g_attn[base2 + P1[tig]] = __uint_as_float(f2tf(o[nt][3] * inv2));
    }
}

// ---------------------------------------------------------------------------
extern "C" void kernel_launch(void* const* d_in, const int* in_sizes, int n_in,
                              void* d_out, int out_size) {
    (void)in_sizes; (void)n_in; (void)out_size;
    const float* x  = (const float*)d_in[0];
    const float* wq = (const float*)d_in[1];
    const float* wk = (const float*)d_in[2];
    const float* wv = (const float*)d_in[3];
    const float* wo = (const float*)d_in[4];
    float* out = (float*)d_out;

    float *q, *k, *attn, *xr, *wqr, *wkr, *wvr, *wor;
    cudaGetSymbolAddress((void**)&q, g_q);
    cudaGetSymbolAddress((void**)&k, g_k);
    cudaGetSymbolAddress((void**)&attn, g_attn);
    cudaGetSymbolAddress((void**)&xr, g_xr);
    cudaGetSymbolAddress((void**)&wqr, g_wqr);
    cudaGetSymbolAddress((void**)&wkr, g_wkr);
    cudaGetSymbolAddress((void**)&wvr, g_wvr);
    cudaGetSymbolAddress((void**)&wor, g_wor);

    cudaFuncSetAttribute(gemm_qkv_kernel, cudaFuncAttributeMaxDynamicSharedMemorySize, GEMM_SMEM);
    cudaFuncSetAttribute(gemm_kernel, cudaFuncAttributeMaxDynamicSharedMemorySize, GEMM_SMEM);
    cudaFuncSetAttribute(attn_kernel, cudaFuncAttributeMaxDynamicSharedMemorySize, ATTN_SMEM);

    // One-time tf32 round + k-group permute of all GEMM operands
    {
        const int T = 256;
        prep_kernel<<<(SEQ * DIM / 8 + T - 1) / T, T>>>(x, xr, SEQ * DIM / 8);
        prep_kernel<<<(DIM * DIM / 8 + T - 1) / T, T>>>(wq, wqr, DIM * DIM / 8);
        prep_kernel<<<(KVD * DIM / 8 + T - 1) / T, T>>>(wk, wkr, KVD * DIM / 8);
        prep_kernel<<<(KVD * DIM / 8 + T - 1) / T, T>>>(wv, wvr, KVD * DIM / 8);
        prep_kernel<<<(DIM * DIM / 8 + T - 1) / T, T>>>(wo, wor, DIM * DIM / 8);
    }

    // Merged Q/K/V projections: 48 column tiles x 16 row tiles
    gemm_qkv_kernel<<<dim3(48, SEQ / 128), 128, GEMM_SMEM>>>();

    // RoPE on q and k (writes tf32-rounded)
    rope_kernel<<<(SEQ * NH * 64) / 256, 256>>>(q, NH);
    rope_kernel<<<(SEQ * NKV * 64) / 256, 256>>>(k, NKV);

    // Attention: 32 q-tiles (64 rows) x 32 heads, longest-first
    attn_kernel<<<dim3(SEQ / 64, NH), 128, ATTN_SMEM>>>();

    // Output projection straight into d_out
    gemm_kernel<<<dim3(DIM / 128, SEQ / 128), 128, GEMM_SMEM>>>(attn, wor, out, DIM, DIM, 0);
}

// round 8
// speedup vs baseline: 1.5445x; 1.0092x over previous
#include <cuda_runtime.h>
#include <cuda_bf16.h>
#include <cstdint>
#include <cstdio>

#define SEQ 2048
#define DIM 4096
#define NH 32
#define NKV 8
#define HD 128
#define KVD (NKV*HD)   // 1024

__device__ float g_q[SEQ * DIM];       // 32 MB (tf32-rounded after rope)
__device__ float g_k[SEQ * KVD];       // 8 MB  (tf32-rounded after rope)
__device__ float g_v[SEQ * KVD];       // 8 MB  (tf32-rounded by V epilogue)
__device__ float g_attn[SEQ * DIM];    // 32 MB (tf32-rounded + k-permuted)
__device__ float g_xr[SEQ * DIM];      // 32 MB
__device__ float g_wqr[DIM * DIM];     // 64 MB
__device__ float g_wkr[KVD * DIM];     // 16 MB
__device__ float g_wvr[KVD * DIM];     // 16 MB
__device__ float g_wor[DIM * DIM];     // 64 MB

__device__ __forceinline__ uint32_t f2tf(float f) {
    uint32_t u;
    asm("cvt.rna.tf32.f32 %0, %1;" : "=r"(u) : "f"(f));
    return u;
}

__device__ __forceinline__ void mma_tf32(float* d,
                                         uint32_t a0, uint32_t a1, uint32_t a2, uint32_t a3,
                                         uint32_t b0, uint32_t b1) {
    asm volatile(
        "mma.sync.aligned.m16n8k8.row.col.f32.tf32.tf32.f32 "
        "{%0,%1,%2,%3}, {%4,%5,%6,%7}, {%8,%9}, {%0,%1,%2,%3};"
        : "+f"(d[0]), "+f"(d[1]), "+f"(d[2]), "+f"(d[3])
        : "r"(a0), "r"(a1), "r"(a2), "r"(a3), "r"(b0), "r"(b1));
}

__device__ __forceinline__ void cp_async16(uint32_t smem_addr, const void* gptr) {
    asm volatile("cp.async.cg.shared.global [%0], [%1], 16;"
                 :: "r"(smem_addr), "l"(gptr) : "memory");
}
#define CP_COMMIT() asm volatile("cp.async.commit_group;" ::: "memory")
#define CP_WAIT(n)  asm volatile("cp.async.wait_group %0;" :: "n"(n) : "memory")

__device__ __forceinline__ uint32_t smem_u32(const void* p) {
    uint32_t a;
    asm("{ .reg .u64 t; cvta.to.shared.u64 t, %1; cvt.u32.u64 %0, t; }" : "=r"(a) : "l"(p));
    return a;
}

// ---------------------------------------------------------------------------
// Prep: round fp32->tf32 AND permute columns within each 8-float k-group:
// src col c lands at (c&3)*2 + (c>>2)  ->  LDS.64 fragment pairs in GEMMs.
// ---------------------------------------------------------------------------
__global__ void prep_kernel(const float* __restrict__ src, float* __restrict__ dst, int ngroups) {
    int g = blockIdx.x * blockDim.x + threadIdx.x;
    if (g >= ngroups) return;
    const float4* s = (const float4*)src + (size_t)g * 2;
    float4 lo = s[0], hi = s[1];
    uint4 o0, o1;
    o0.x = f2tf(lo.x); o0.y = f2tf(hi.x); o0.z = f2tf(lo.y); o0.w = f2tf(hi.y);
    o1.x = f2tf(lo.z); o1.y = f2tf(hi.z); o1.z = f2tf(lo.w); o1.w = f2tf(hi.w);
    uint4* d = (uint4*)dst + (size_t)g * 2;
    d[0] = o0; d[1] = o1;
}

// ---------------------------------------------------------------------------
// GEMM core: C[M,N] = A[M,K] @ B[N,K]^T (pre-rounded + k-permuted operands).
// CTA tile 128x128, 4 warps of 64x64 (2x2), K-chunk 32, 2-stage cp.async,
// LDS.64 fragments at row stride 40 (conflict-free), 2 CTAs/SM.
// ---------------------------------------------------------------------------
#define KC 32
#define ST 40
#define A_STG (128 * ST)
#define B_STG (128 * ST)
#define GEMM_SMEM (2 * (A_STG + B_STG) * 4)   // 81920 B

__device__ __forceinline__ void gemm_body(
    const float* __restrict__ A, const float* __restrict__ B,
    float* __restrict__ C, int N, int K, int round_out,
    int bm, int bn, float* smem)
{
    float* As[2]; float* Bs[2];
#pragma unroll
    for (int s = 0; s < 2; s++) {
        As[s] = smem + s * (A_STG + B_STG);
        Bs[s] = As[s] + A_STG;
    }

    const int tid  = threadIdx.x;
    const int warp = tid >> 5, lane = tid & 31;
    const int gid  = lane >> 2, tig = lane & 3;
    const int wm   = warp >> 1, wn = warp & 1;   // 2x2 warps, warp tile 64x64

    const float* Ab = A + (size_t)(bm * 128) * K;
    const float* Bb = B + (size_t)(bn * 128) * K;

    auto issue = [&](int kt, int s) {
        const float* Ak = Ab + kt * KC;
        const float* Bk = Bb + kt * KC;
        uint32_t as = smem_u32(As[s]);
        uint32_t bs = smem_u32(Bs[s]);
#pragma unroll
        for (int i = 0; i < 8; i++) {
            int idx = tid + i * 128;
            int r = idx >> 3, c = idx & 7;
            cp_async16(as + (r * ST + c * 4) * 4, Ak + (size_t)r * K + c * 4);
        }
#pragma unroll
        for (int i = 0; i < 8; i++) {
            int idx = tid + i * 128;
            int r = idx >> 3, c = idx & 7;
            cp_async16(bs + (r * ST + c * 4) * 4, Bk + (size_t)r * K + c * 4);
        }
        CP_COMMIT();
    };

    float acc[4][8][4];
#pragma unroll
    for (int i = 0; i < 4; i++)
#pragma unroll
        for (int j = 0; j < 8; j++)
#pragma unroll
            for (int q = 0; q < 4; q++) acc[i][j][q] = 0.f;

    const int nk = K / KC;
    issue(0, 0);

    for (int kt = 0; kt < nk; ++kt) {
        const int s = kt & 1;
        if (kt + 1 < nk) {
            issue(kt + 1, s ^ 1);
            CP_WAIT(1);
        } else {
            CP_WAIT(0);
        }
        __syncthreads();

        const float* as = As[s];
        const float* bs = Bs[s];
#pragma unroll
        for (int ks = 0; ks < 4; ++ks) {
            const int kk = ks * 8;
            uint32_t af[4][4], bf[8][2];
#pragma unroll
            for (int mi = 0; mi < 4; ++mi) {
                int r = wm * 64 + mi * 16;
                uint2 p1 = *(const uint2*)&as[(r + gid)     * ST + kk + 2 * tig];
                uint2 p2 = *(const uint2*)&as[(r + gid + 8) * ST + kk + 2 * tig];
                af[mi][0] = p1.x; af[mi][1] = p2.x; af[mi][2] = p1.y; af[mi][3] = p2.y;
            }
#pragma unroll
            for (int ni = 0; ni < 8; ++ni) {
                int c = wn * 64 + ni * 8;
                uint2 q = *(const uint2*)&bs[(c + gid) * ST + kk + 2 * tig];
                bf[ni][0] = q.x; bf[ni][1] = q.y;
            }
#pragma unroll
            for (int mi = 0; mi < 4; ++mi)
#pragma unroll
                for (int ni = 0; ni < 8; ++ni)
                    mma_tf32(acc[mi][ni], af[mi][0], af[mi][1], af[mi][2], af[mi][3],
                             bf[ni][0], bf[ni][1]);
        }
        __syncthreads();
    }

#pragma unroll
    for (int mi = 0; mi < 4; ++mi) {
        int r0 = bm * 128 + wm * 64 + mi * 16 + gid;
#pragma unroll
        for (int ni = 0; ni < 8; ++ni) {
            int c0 = bn * 128 + wn * 64 + ni * 8 + tig * 2;
            if (round_out) {
                uint2 v1, v2;
                v1.x = f2tf(acc[mi][ni][0]); v1.y = f2tf(acc[mi][ni][1]);
                v2.x = f2tf(acc[mi][ni][2]); v2.y = f2tf(acc[mi][ni][3]);
                *(uint2*)&C[(size_t)r0 * N + c0]       = v1;
                *(uint2*)&C[(size_t)(r0 + 8) * N + c0] = v2;
            } else {
                *(float2*)&C[(size_t)r0 * N + c0]       = make_float2(acc[mi][ni][0], acc[mi][ni][1]);
                *(float2*)&C[(size_t)(r0 + 8) * N + c0] = make_float2(acc[mi][ni][2], acc[mi][ni][3]);
            }
        }
    }
}

// Merged Q/K/V projection: grid.x = 48 column tiles (q:0-31, k:32-39, v:40-47)
__global__ void __launch_bounds__(128, 2) gemm_qkv_kernel() {
    extern __shared__ float smem[];
    int bx = blockIdx.x, bm = blockIdx.y;
    const float* B; float* C; int N, bn, ro;
    if (bx < 32)      { B = g_wqr; C = g_q; N = DIM; bn = bx;      ro = 0; }
    else if (bx < 40) { B = g_wkr; C = g_k; N = KVD; bn = bx - 32; ro = 0; }
    else              { B = g_wvr; C = g_v; N = KVD; bn = bx - 40; ro = 1; }
    gemm_body(g_xr, B, C, N, DIM, ro, bm, bn, smem);
}

__global__ void __launch_bounds__(128, 2) gemm_kernel(
    const float* __restrict__ A, const float* __restrict__ B,
    float* __restrict__ C, int N, int K, int round_out)
{
    extern __shared__ float smem[];
    gemm_body(A, B, C, N, K, round_out, blockIdx.y, blockIdx.x, smem);
}

// ---------------------------------------------------------------------------
// RoPE: fp32 angle math; writes tf32-rounded output.
// ---------------------------------------------------------------------------
__global__ void rope_kernel(float* __restrict__ t, int H) {
    int idx = blockIdx.x * blockDim.x + threadIdx.x;
    int total = SEQ * H * 64;
    if (idx >= total) return;
    int i  = idx & 63;
    int tp = idx >> 6;
    int hh = tp % H;
    int s  = tp / H;

    float freq = exp2f(-(float)i * (18.931568569324174f / 64.0f));
    float ang = (float)s * freq;
    float sn, cs;
    sincosf(ang, &sn, &cs);

    float* p = t + (size_t)s * (H * HD) + hh * HD + 2 * i;
    float x0 = p[0], x1 = p[1];
    uint2 o;
    o.x = f2tf(x0 * cs - x1 * sn);
    o.y = f2tf(x0 * sn + x1 * cs);
    *(uint2*)p = o;
}

// ---------------------------------------------------------------------------
// Flash attention v3 (causal, GQA group=4), legacy tf32 mma.
// CTA = 128 q-rows x one head; kv tile 32; 4 warps x 32 q-rows.
// XOR-swizzled smem (stride 128, no padding): Q/K/P keyed (r&7)<<2,
// V keyed (r&7)<<3 -> all fragment loads conflict-free.
// P overwrites the K region after QK (flat 4096-word region).
// smem 96 KB -> 2 CTAs/SM. Per-warp skip of fully masked diagonal blocks.
// ---------------------------------------------------------------------------
#define ATTN_SMEM (24576 * 4)   // 98304 B

__device__ __forceinline__ int swq(int r, int c) { return r * 128 + (c ^ ((r & 7) << 2)); }
__device__ __forceinline__ int swv(int r, int c) { return r * 128 + (c ^ ((r & 7) << 3)); }
__device__ __forceinline__ int swp(int r, int c) { return r * 32  + (c ^ ((r & 7) << 2)); }

__global__ void __launch_bounds__(128, 2) attn_kernel() {
    extern __shared__ uint32_t sm[];
    uint32_t* Qs = sm;            // 128 x 128 (swq)
    uint32_t* T1 = sm + 16384;    // K: 32 x 128 (swq) -> P: 128 x 32 (swp)
    uint32_t* Vs = sm + 20480;    // V: 32 x 128 (swv)
    const uint32_t qb_ = smem_u32(sm);
    const uint32_t t1b = smem_u32(T1);
    const uint32_t vb_ = smem_u32(Vs);

    const int qt  = 15 - (int)blockIdx.x;      // longest first
    const int h   = blockIdx.y;
    const int kvh = h >> 2;
    const int q0  = qt * 128;
    const int tid = threadIdx.x;
    const int w   = tid >> 5, lane = tid & 31;
    const int gid = lane >> 2, tig = lane & 3;
    const int wr  = w * 32;                     // warp's first local q row

    // Q tile 128x128 via cp.async (already tf32-rounded)
#pragma unroll
    for (int i = 0; i < 32; i++) {
        int idx = tid + i * 128;                // 128 rows x 32 x 16B
        int r = idx >> 5, c = (idx & 31) << 2;
        cp_async16(qb_ + 4 * (r * 128 + (c ^ ((r & 7) << 2))),
                   &g_q[(size_t)(q0 + r) * DIM + h * HD + c]);
    }
    CP_COMMIT();

    float o[2][16][4];
#pragma unroll
    for (int m = 0; m < 2; m++)
#pragma unroll
        for (int j = 0; j < 16; j++)
#pragma unroll
            for (int q = 0; q < 4; q++) o[m][j][q] = 0.f;
    float mx[2][2] = {{-1e30f, -1e30f}, {-1e30f, -1e30f}};
    float ls[2][2] = {{0.f, 0.f}, {0.f, 0.f}};

    const int nkb = 4 * (qt + 1);
    for (int kb = 0; kb < nkb; ++kb) {
        const int d = kb - 4 * qt;              // >=0 only on diagonal band
        __syncthreads();                        // prior iter's T1/V readers done

        // K -> T1, V -> Vs (32 rows x 128 cols each) via cp.async
#pragma unroll
        for (int i = 0; i < 8; i++) {
            int idx = tid + i * 128;            // 32 rows x 32 x 16B
            int r = idx >> 5, c = (idx & 31) << 2;
            const float* kg = &g_k[(size_t)(kb * 32 + r) * KVD + kvh * HD + c];
            const float* vg = &g_v[(size_t)(kb * 32 + r) * KVD + kvh * HD + c];
            cp_async16(t1b + 4 * (r * 128 + (c ^ ((r & 7) << 2))), kg);
            cp_async16(vb_ + 4 * (r * 128 + (c ^ ((r & 7) << 3))), vg);
        }
        CP_COMMIT();
        CP_WAIT(0);
        __syncthreads();

        const bool skip = (d > w);              // fully masked for this warp
        float s[2][4][4];
        if (!skip) {
#pragma unroll
            for (int m = 0; m < 2; m++)
#pragma unroll
                for (int j = 0; j < 4; j++)
#pragma unroll
                    for (int q = 0; q < 4; q++) s[m][j][q] = 0.f;

#pragma unroll 4
            for (int ks = 0; ks < 16; ++ks) {
                const int kk = ks * 8;
                uint32_t af[2][4], bf[4][2];
#pragma unroll
                for (int m = 0; m < 2; m++) {
                    int r = wr + m * 16 + gid;
                    af[m][0] = Qs[swq(r,     kk + tig)];
                    af[m][1] = Qs[swq(r + 8, kk + tig)];
                    af[m][2] = Qs[swq(r,     kk + tig + 4)];
                    af[m][3] = Qs[swq(r + 8, kk + tig + 4)];
                }
#pragma unroll
                for (int nt = 0; nt < 4; ++nt) {
                    int c = nt * 8 + gid;
                    bf[nt][0] = T1[swq(c, kk + tig)];
                    bf[nt][1] = T1[swq(c, kk + tig + 4)];
                }
#pragma unroll
                for (int m = 0; m < 2; m++)
#pragma unroll
                    for (int nt = 0; nt < 4; ++nt)
                        mma_tf32(s[m][nt], af[m][0], af[m][1], af[m][2], af[m][3],
                                 bf[nt][0], bf[nt][1]);
            }
        }
        __syncthreads();                        // all K reads done; T1 becomes P

        if (!skip) {
            const float scale = 0.08838834764831845f;  // 1/sqrt(128)
            if (d == w) {                       // diagonal 32x32 sub-block
#pragma unroll
                for (int m = 0; m < 2; m++) {
                    int r1 = m * 16 + gid, r2 = r1 + 8;
#pragma unroll
                    for (int nt = 0; nt < 4; ++nt) {
                        int c0 = nt * 8 + tig * 2;
                        s[m][nt][0] = (c0     <= r1) ? s[m][nt][0] * scale : -1e30f;
                        s[m][nt][1] = (c0 + 1 <= r1) ? s[m][nt][1] * scale : -1e30f;
                        s[m][nt][2] = (c0     <= r2) ? s[m][nt][2] * scale : -1e30f;
                        s[m][nt][3] = (c0 + 1 <= r2) ? s[m][nt][3] * scale : -1e30f;
                    }
                }
            } else {
#pragma unroll
                for (int m = 0; m < 2; m++)
#pragma unroll
                    for (int nt = 0; nt < 4; ++nt) {
                        s[m][nt][0] *= scale; s[m][nt][1] *= scale;
                        s[m][nt][2] *= scale; s[m][nt][3] *= scale;
                    }
            }

#pragma unroll
            for (int m = 0; m < 2; m++) {
                float m1 = -1e30f, m2 = -1e30f;
#pragma unroll
                for (int nt = 0; nt < 4; ++nt) {
                    m1 = fmaxf(m1, fmaxf(s[m][nt][0], s[m][nt][1]));
                    m2 = fmaxf(m2, fmaxf(s[m][nt][2], s[m][nt][3]));
                }
                m1 = fmaxf(m1, __shfl_xor_sync(0xffffffffu, m1, 1));
                m1 = fmaxf(m1, __shfl_xor_sync(0xffffffffu, m1, 2));
                m2 = fmaxf(m2, __shfl_xor_sync(0xffffffffu, m2, 1));
                m2 = fmaxf(m2, __shfl_xor_sync(0xffffffffu, m2, 2));

                float nm1 = fmaxf(mx[m][0], m1), nm2 = fmaxf(mx[m][1], m2);
                float al1 = __expf(mx[m][0] - nm1), al2 = __expf(mx[m][1] - nm2);
                float sum1 = 0.f, sum2 = 0.f;
#pragma unroll
                for (int nt = 0; nt < 4; ++nt) {
                    s[m][nt][0] = __expf(s[m][nt][0] - nm1); sum1 += s[m][nt][0];
                    s[m][nt][1] = __expf(s[m][nt][1] - nm1); sum1 += s[m][nt][1];
                    s[m][nt][2] = __expf(s[m][nt][2] - nm2); sum2 += s[m][nt][2];
                    s[m][nt][3] = __expf(s[m][nt][3] - nm2); sum2 += s[m][nt][3];
                }
                sum1 += __shfl_xor_sync(0xffffffffu, sum1, 1);
                sum1 += __shfl_xor_sync(0xffffffffu, sum1, 2);
                sum2 += __shfl_xor_sync(0xffffffffu, sum2, 1);
                sum2 += __shfl_xor_sync(0xffffffffu, sum2, 2);

                ls[m][0] = ls[m][0] * al1 + sum1; mx[m][0] = nm1;
                ls[m][1] = ls[m][1] * al2 + sum2; mx[m][1] = nm2;
#pragma unroll
                for (int nt = 0; nt < 16; ++nt) {
                    o[m][nt][0] *= al1; o[m][nt][1] *= al1;
                    o[m][nt][2] *= al2; o[m][nt][3] *= al2;
                }

                // write P rows (warp-private) into T1 (flat, stride 32, swp)
                int rA = wr + m * 16 + gid, rB = rA + 8;
#pragma unroll
                for (int nt = 0; nt < 4; ++nt) {
                    int c0 = nt * 8 + tig * 2;
                    T1[swp(rA, c0)]     = f2tf(s[m][nt][0]);
                    T1[swp(rA, c0 + 1)] = f2tf(s[m][nt][1]);
                    T1[swp(rB, c0)]     = f2tf(s[m][nt][2]);
                    T1[swp(rB, c0 + 1)] = f2tf(s[m][nt][3]);
                }
            }
            __syncwarp();

            // o += P @ V (k-dim = 32 kv)
#pragma unroll
            for (int ks = 0; ks < 4; ++ks) {
                const int kk = ks * 8;
                uint32_t af[2][4];
#pragma unroll
                for (int m = 0; m < 2; m++) {
                    int r = wr + m * 16 + gid;
                    af[m][0] = T1[swp(r,     kk + tig)];
                    af[m][1] = T1[swp(r + 8, kk + tig)];
                    af[m][2] = T1[swp(r,     kk + tig + 4)];
                    af[m][3] = T1[swp(r + 8, kk + tig + 4)];
                }
#pragma unroll
                for (int nt = 0; nt < 16; ++nt) {
                    int n0 = nt * 8;
                    uint32_t b0 = Vs[swv(kk + tig,     n0 + gid)];
                    uint32_t b1 = Vs[swv(kk + tig + 4, n0 + gid)];
#pragma unroll
                    for (int m = 0; m < 2; m++)
                        mma_tf32(o[m][nt], af[m][0], af[m][1], af[m][2], af[m][3], b0, b1);
                }
            }
        }
    }

    // epilogue: tf32-round AND k-group-permute for the O-GEMM A operand.
    const int P0[4] = {0, 4, 1, 5};
    const int P1[4] = {2, 6, 3, 7};
#pragma unroll
    for (int m = 0; m < 2; m++) {
        const float inv1 = 1.f / ls[m][0], inv2 = 1.f / ls[m][1];
        const int r1 = q0 + wr + m * 16 + gid;
#pragma unroll
        for (int nt = 0; nt < 16; ++nt) {
            size_t base1 = (size_t)r1 * DIM + h * HD + nt * 8;
            size_t base2 = (size_t)(r1 + 8) * DIM + h * HD + nt * 8;
            g_attn[base1 + P0[tig]] = __uint_as_float(f2tf(o[m][nt][0] * inv1));
            g_attn[base1 + P1[tig]] = __uint_as_float(f2tf(o[m][nt][1] * inv1));
            g_attn[base2 + P0[tig]] = __uint_as_float(f2tf(o[m][nt][2] * inv2));
            g_attn[base2 + P1[tig]] = __uint_as_float(f2tf(o[m][nt][3] * inv2));
        }
    }
}

// ---------------------------------------------------------------------------
extern "C" void kernel_launch(void* const* d_in, const int* in_sizes, int n_in,
                              void* d_out, int out_size) {
    (void)in_sizes; (void)n_in; (void)out_size;
    const float* x  = (const float*)d_in[0];
    const float* wq = (const float*)d_in[1];
    const float* wk = (const float*)d_in[2];
    const float* wv = (const float*)d_in[3];
    const float* wo = (const float*)d_in[4];
    float* out = (float*)d_out;

    float *q, *k, *attn, *xr, *wqr, *wkr, *wvr, *wor;
    cudaGetSymbolAddress((void**)&q, g_q);
    cudaGetSymbolAddress((void**)&k, g_k);
    cudaGetSymbolAddress((void**)&attn, g_attn);
    cudaGetSymbolAddress((void**)&xr, g_xr);
    cudaGetSymbolAddress((void**)&wqr, g_wqr);
    cudaGetSymbolAddress((void**)&wkr, g_wkr);
    cudaGetSymbolAddress((void**)&wvr, g_wvr);
    cudaGetSymbolAddress((void**)&wor, g_wor);

    cudaFuncSetAttribute(gemm_qkv_kernel, cudaFuncAttributeMaxDynamicSharedMemorySize, GEMM_SMEM);
    cudaFuncSetAttribute(gemm_kernel, cudaFuncAttributeMaxDynamicSharedMemorySize, GEMM_SMEM);
    cudaFuncSetAttribute(attn_kernel, cudaFuncAttributeMaxDynamicSharedMemorySize, ATTN_SMEM);

    {
        const int T = 256;
        prep_kernel<<<(SEQ * DIM / 8 + T - 1) / T, T>>>(x, xr, SEQ * DIM / 8);
        prep_kernel<<<(DIM * DIM / 8 + T - 1) / T, T>>>(wq, wqr, DIM * DIM / 8);
        prep_kernel<<<(KVD * DIM / 8 + T - 1) / T, T>>>(wk, wkr, KVD * DIM / 8);
        prep_kernel<<<(KVD * DIM / 8 + T - 1) / T, T>>>(wv, wvr, KVD * DIM / 8);
        prep_kernel<<<(DIM * DIM / 8 + T - 1) / T, T>>>(wo, wor, DIM * DIM / 8);
    }

    // Merged Q/K/V projections
    gemm_qkv_kernel<<<dim3(48, SEQ / 128), 128, GEMM_SMEM>>>();

    // RoPE on q and k (writes tf32-rounded)
    rope_kernel<<<(SEQ * NH * 64) / 256, 256>>>(q, NH);
    rope_kernel<<<(SEQ * NKV * 64) / 256, 256>>>(k, NKV);

    // Attention: 16 q-tiles (128 rows) x 32 heads, longest-first
    attn_kernel<<<dim3(SEQ / 128, NH), 128, ATTN_SMEM>>>();

    // Output projection straight into d_out
    gemm_kernel<<<dim3(DIM / 128, SEQ / 128), 128, GEMM_SMEM>>>(attn, wor, out, DIM, DIM, 0);
}

// round 9
// speedup vs baseline: 2.4489x; 1.5855x over previous
#include <cuda_runtime.h>
#include <cuda_fp16.h>
#include <cstdint>
#include <cstdio>

#define SEQ 2048
#define DIM 4096
#define NH 32
#define NKV 8
#define HD 128
#define KVD (NKV*HD)   // 1024

// fp32 intermediates (projection outputs, pre-rope)
__device__ float  g_q[SEQ * DIM];        // 32 MB
__device__ float  g_k[SEQ * KVD];        // 8 MB
// fp16 operands
__device__ __half g_qh[SEQ * DIM];       // 16 MB (rope out, pair-permuted head dim)
__device__ __half g_kh[SEQ * KVD];       // 4 MB  (rope out, pair-permuted head dim)
__device__ __half g_vT[KVD * SEQ];       // 4 MB  (V transposed: [head col][seq])
__device__ __half g_attnh[SEQ * DIM];    // 16 MB (attn out, pair-permuted)
__device__ __half g_xh[SEQ * DIM];       // 16 MB (prep: fp16 + pair-permute)
__device__ __half g_wqh[DIM * DIM];      // 32 MB
__device__ __half g_wkh[KVD * DIM];      // 8 MB
__device__ __half g_wvh[KVD * DIM];      // 8 MB
__device__ __half g_woh[DIM * DIM];      // 32 MB

__device__ __forceinline__ void mma_f16(float* d,
                                        uint32_t a0, uint32_t a1, uint32_t a2, uint32_t a3,
                                        uint32_t b0, uint32_t b1) {
    asm volatile(
        "mma.sync.aligned.m16n8k16.row.col.f32.f16.f16.f32 "
        "{%0,%1,%2,%3}, {%4,%5,%6,%7}, {%8,%9}, {%0,%1,%2,%3};"
        : "+f"(d[0]), "+f"(d[1]), "+f"(d[2]), "+f"(d[3])
        : "r"(a0), "r"(a1), "r"(a2), "r"(a3), "r"(b0), "r"(b1));
}

__device__ __forceinline__ void cp_async16(uint32_t smem_addr, const void* gptr) {
    asm volatile("cp.async.cg.shared.global [%0], [%1], 16;"
                 :: "r"(smem_addr), "l"(gptr) : "memory");
}
#define CP_COMMIT() asm volatile("cp.async.commit_group;" ::: "memory")
#define CP_WAIT(n)  asm volatile("cp.async.wait_group %0;" :: "n"(n) : "memory")

__device__ __forceinline__ uint32_t smem_u32(const void* p) {
    uint32_t a;
    asm("{ .reg .u64 t; cvta.to.shared.u64 t, %1; cvt.u32.u64 %0, t; }" : "=r"(a) : "l"(p));
    return a;
}

// ---------------------------------------------------------------------------
// Prep: fp32 -> fp16 with pair-permute within each 16-element k-group:
// pair j (elements 2j,2j+1) lands at pair position (j&3)*2 + (j>>2).
// Makes m16n8k16 fragment halves {k,k+1,k+8,k+9} contiguous -> LDS.64.
// ---------------------------------------------------------------------------
__global__ void prep_kernel(const float* __restrict__ src, __half* __restrict__ dst, int ngroups) {
    int g = blockIdx.x * blockDim.x + threadIdx.x;
    if (g >= ngroups) return;
    const float4* s = (const float4*)src + (size_t)g * 4;
    float4 f0 = s[0], f1 = s[1], f2 = s[2], f3 = s[3];
    __half2* d = (__half2*)dst + (size_t)g * 8;
    // src pairs p0..p7 -> out order [p0,p4,p1,p5,p2,p6,p3,p7]
    d[0] = __floats2half2_rn(f0.x, f0.y);
    d[1] = __floats2half2_rn(f2.x, f2.y);
    d[2] = __floats2half2_rn(f0.z, f0.w);
    d[3] = __floats2half2_rn(f2.z, f2.w);
    d[4] = __floats2half2_rn(f1.x, f1.y);
    d[5] = __floats2half2_rn(f3.x, f3.y);
    d[6] = __floats2half2_rn(f1.z, f1.w);
    d[7] = __floats2half2_rn(f3.z, f3.w);
}

// ---------------------------------------------------------------------------
// fp16 GEMM core: C[M,N] = A[M,K] @ B[N,K]^T (fp16, pair-permuted k).
// CTA 128x128, 4 warps of 64x64, K-chunk 32 halfs (2 k16 steps),
// 2-stage cp.async, LDS.64 fragments (row stride 48 halfs, conflict-free).
// mode 0: fp32 plain store. mode 1: fp16 transposed store into g_vT.
// ---------------------------------------------------------------------------
#define KC 32
#define STH 48                            // halfs per smem row
#define STG_B (128 * STH * 2)             // 12288 B per tile stage
#define GEMM_SMEM (4 * STG_B)             // 49152 B

__device__ __forceinline__ void gemm_body(
    const __half* __restrict__ A, const __half* __restrict__ B,
    float* __restrict__ C, int N, int K, int mode,
    int bm, int bn, char* smem)
{
    char* As[2]; char* Bs[2];
#pragma unroll
    for (int s = 0; s < 2; s++) {
        As[s] = smem + s * 2 * STG_B;
        Bs[s] = As[s] + STG_B;
    }

    const int tid  = threadIdx.x;
    const int warp = tid >> 5, lane = tid & 31;
    const int gid  = lane >> 2, tig = lane & 3;
    const int wm   = warp >> 1, wn = warp & 1;   // 2x2 warps, 64x64 tiles

    const __half* Ab = A + (size_t)(bm * 128) * K;
    const __half* Bb = B + (size_t)(bn * 128) * K;

    auto issue = [&](int kt, int s) {
        const __half* Ak = Ab + kt * KC;
        const __half* Bk = Bb + kt * KC;
        uint32_t as = smem_u32(As[s]);
        uint32_t bs = smem_u32(Bs[s]);
#pragma unroll
        for (int i = 0; i < 4; i++) {            // 128 rows x 4 x 16B
            int idx = tid + i * 128;
            int r = idx >> 2, c = idx & 3;
            cp_async16(as + r * 96 + c * 16, Ak + (size_t)r * K + c * 8);
        }
#pragma unroll
        for (int i = 0; i < 4; i++) {
            int idx = tid + i * 128;
            int r = idx >> 2, c = idx & 3;
            cp_async16(bs + r * 96 + c * 16, Bk + (size_t)r * K + c * 8);
        }
        CP_COMMIT();
    };

    float acc[4][8][4];
#pragma unroll
    for (int i = 0; i < 4; i++)
#pragma unroll
        for (int j = 0; j < 8; j++)
#pragma unroll
            for (int q = 0; q < 4; q++) acc[i][j][q] = 0.f;

    const int nk = K / KC;
    issue(0, 0);

    for (int kt = 0; kt < nk; ++kt) {
        const int s = kt & 1;
        if (kt + 1 < nk) {
            issue(kt + 1, s ^ 1);
            CP_WAIT(1);
        } else {
            CP_WAIT(0);
        }
        __syncthreads();

        const char* as = As[s];
        const char* bs = Bs[s];
#pragma unroll
        for (int ks = 0; ks < 2; ++ks) {
            uint32_t af[4][4], bf[8][2];
#pragma unroll
            for (int mi = 0; mi < 4; ++mi) {
                int r = wm * 64 + mi * 16;
                uint2 p1 = *(const uint2*)(as + (r + gid)     * 96 + 32 * ks + 8 * tig);
                uint2 p2 = *(const uint2*)(as + (r + gid + 8) * 96 + 32 * ks + 8 * tig);
                af[mi][0] = p1.x; af[mi][1] = p2.x; af[mi][2] = p1.y; af[mi][3] = p2.y;
            }
#pragma unroll
            for (int ni = 0; ni < 8; ++ni) {
                int c = wn * 64 + ni * 8;
                uint2 q = *(const uint2*)(bs + (c + gid) * 96 + 32 * ks + 8 * tig);
                bf[ni][0] = q.x; bf[ni][1] = q.y;
            }
#pragma unroll
            for (int mi = 0; mi < 4; ++mi)
#pragma unroll
                for (int ni = 0; ni < 8; ++ni)
                    mma_f16(acc[mi][ni], af[mi][0], af[mi][1], af[mi][2], af[mi][3],
                            bf[ni][0], bf[ni][1]);
        }
        __syncthreads();
    }

#pragma unroll
    for (int mi = 0; mi < 4; ++mi) {
        int r0 = bm * 128 + wm * 64 + mi * 16 + gid;
#pragma unroll
        for (int ni = 0; ni < 8; ++ni) {
            int c0 = bn * 128 + wn * 64 + ni * 8 + tig * 2;
            if (mode == 0) {
                *(float2*)&C[(size_t)r0 * N + c0]       = make_float2(acc[mi][ni][0], acc[mi][ni][1]);
                *(float2*)&C[(size_t)(r0 + 8) * N + c0] = make_float2(acc[mi][ni][2], acc[mi][ni][3]);
            } else {   // V: fp16 transposed into g_vT[col][seq]
                g_vT[(size_t)c0 * SEQ + r0]           = __float2half_rn(acc[mi][ni][0]);
                g_vT[(size_t)(c0 + 1) * SEQ + r0]     = __float2half_rn(acc[mi][ni][1]);
                g_vT[(size_t)c0 * SEQ + r0 + 8]       = __float2half_rn(acc[mi][ni][2]);
                g_vT[(size_t)(c0 + 1) * SEQ + r0 + 8] = __float2half_rn(acc[mi][ni][3]);
            }
        }
    }
}

// Merged Q/K/V projection: grid.x = 48 col tiles (q:0-31, k:32-39, v:40-47)
__global__ void __launch_bounds__(128, 2) gemm_qkv_kernel() {
    extern __shared__ char smem[];
    int bx = blockIdx.x, bm = blockIdx.y;
    const __half* B; float* C; int N, bn, mode;
    if (bx < 32)      { B = g_wqh; C = g_q;  N = DIM; bn = bx;      mode = 0; }
    else if (bx < 40) { B = g_wkh; C = g_k;  N = KVD; bn = bx - 32; mode = 0; }
    else              { B = g_wvh; C = 0;    N = KVD; bn = bx - 40; mode = 1; }
    gemm_body(g_xh, B, C, N, DIM, mode, bm, bn, smem);
}

__global__ void __launch_bounds__(128, 2) gemm_kernel(
    const __half* __restrict__ A, const __half* __restrict__ B,
    float* __restrict__ C, int N, int K)
{
    extern __shared__ char smem[];
    gemm_body(A, B, C, N, K, 0, blockIdx.y, blockIdx.x, smem);
}

// ---------------------------------------------------------------------------
// RoPE: fp32 angle math, reads fp32 proj output, writes fp16 pair-permuted.
// ---------------------------------------------------------------------------
__global__ void rope_kernel(const float* __restrict__ src, __half* __restrict__ dst, int H) {
    int idx = blockIdx.x * blockDim.x + threadIdx.x;
    int total = SEQ * H * 64;
    if (idx >= total) return;
    int i  = idx & 63;
    int tp = idx >> 6;
    int hh = tp % H;
    int s  = tp / H;

    float freq = exp2f(-(float)i * (18.931568569324174f / 64.0f));
    float ang = (float)s * freq;
    float sn, cs;
    sincosf(ang, &sn, &cs);

    const float* p = src + (size_t)s * (H * HD) + hh * HD + 2 * i;
    float x0 = p[0], x1 = p[1];
    float r0 = x0 * cs - x1 * sn;
    float r1 = x0 * sn + x1 * cs;

    // pair-permute: pair i -> grp*8 + (j&3)*2 + (j>>2), j = i&7
    int grp = i >> 3, j = i & 7;
    int dst_el = grp * 16 + (((j & 3) * 2 + (j >> 2)) << 1);
    *(__half2*)&dst[(size_t)s * (H * HD) + hh * HD + dst_el] = __floats2half2_rn(r0, r1);
}

// ---------------------------------------------------------------------------
// Flash attention (causal, GQA group=4), fp16 m16n8k16 mma.
// CTA = 128 q-rows x head; kv tile 32; 4 warps x 32 q-rows; 3 CTAs/SM.
// Q/K smem: 256B rows, XOR swizzle on 8B granules (g8 ^= (r&3)<<2).
// P, V^T smem: stride 40 halfs (conflict-free LDS.32).
// ---------------------------------------------------------------------------
#define SM_Q   0            // 128 x 256B = 32768
#define SM_K   32768        // 32 x 256B  = 8192
#define SM_P   40960        // 128 x 40 halfs = 10240
#define SM_VT  51200        // 128 x 40 halfs = 10240
#define ATTN_SMEM 61440

__global__ void __launch_bounds__(128, 3) attn_kernel() {
    extern __shared__ char sm[];
    char* smQ = sm + SM_Q;
    char* smK = sm + SM_K;
    __half* Ps  = (__half*)(sm + SM_P);
    __half* VTs = (__half*)(sm + SM_VT);
    const uint32_t qb_ = smem_u32(smQ);
    const uint32_t kb_ = smem_u32(smK);
    const uint32_t vb_ = smem_u32(VTs);

    const int qt  = 15 - (int)blockIdx.x;      // longest first
    const int h   = blockIdx.y;
    const int kvh = h >> 2;
    const int q0  = qt * 128;
    const int tid = threadIdx.x;
    const int w   = tid >> 5, lane = tid & 31;
    const int gid = lane >> 2, tig = lane & 3;
    const int wr  = w * 32;

    // Q tile: 128 rows x 16 chunks of 16B, XOR swizzled
#pragma unroll
    for (int i = 0; i < 16; i++) {
        int idx = tid + i * 128;
        int r = idx >> 4, m = idx & 15;
        cp_async16(qb_ + r * 256 + ((m ^ ((r & 3) << 1)) << 4),
                   &g_qh[(size_t)(q0 + r) * DIM + h * HD + m * 8]);
    }
    CP_COMMIT();

    float o[2][16][4];
#pragma unroll
    for (int m = 0; m < 2; m++)
#pragma unroll
        for (int j = 0; j < 16; j++)
#pragma unroll
            for (int q = 0; q < 4; q++) o[m][j][q] = 0.f;
    float mx[2][2] = {{-1e30f, -1e30f}, {-1e30f, -1e30f}};
    float ls[2][2] = {{0.f, 0.f}, {0.f, 0.f}};

    const int nkb = 4 * (qt + 1);
    for (int kb = 0; kb < nkb; ++kb) {
        const int d = kb - 4 * qt;
        __syncthreads();

        // K tile: 32 rows x 16 chunks; V^T tile: 128 rows x 4 chunks
#pragma unroll
        for (int i = 0; i < 4; i++) {
            int idx = tid + i * 128;
            int r = idx >> 4, m = idx & 15;
            cp_async16(kb_ + r * 256 + ((m ^ ((r & 3) << 1)) << 4),
                       &g_kh[(size_t)(kb * 32 + r) * KVD + kvh * HD + m * 8]);
        }
#pragma unroll
        for (int i = 0; i < 4; i++) {
            int idx = tid + i * 128;
            int r = idx >> 2, c = idx & 3;
            cp_async16(vb_ + r * 80 + c * 16,
                       &g_vT[(size_t)(kvh * HD + r) * SEQ + kb * 32 + c * 8]);
        }
        CP_COMMIT();
        CP_WAIT(0);
        __syncthreads();

        const bool skip = (d > w);
        float s[2][4][4];
        if (!skip) {
#pragma unroll
            for (int m = 0; m < 2; m++)
#pragma unroll
                for (int j = 0; j < 4; j++)
#pragma unroll
                    for (int q = 0; q < 4; q++) s[m][j][q] = 0.f;

            // Q K^T: k-dim 128 -> 8 k16 steps
#pragma unroll
            for (int ks = 0; ks < 8; ++ks) {
                uint32_t af[2][4], bf[4][2];
#pragma unroll
                for (int m = 0; m < 2; m++) {
                    int r = wr + m * 16 + gid;
                    uint2 p1 = *(const uint2*)(smQ + r * 256 + (((4 * ks + tig) ^ ((r & 3) << 2)) << 3));
                    int r2 = r + 8;
                    uint2 p2 = *(const uint2*)(smQ + r2 * 256 + (((4 * ks + tig) ^ ((r2 & 3) << 2)) << 3));
                    af[m][0] = p1.x; af[m][1] = p2.x; af[m][2] = p1.y; af[m][3] = p2.y;
                }
#pragma unroll
                for (int nt = 0; nt < 4; ++nt) {
                    int c = nt * 8 + gid;
                    uint2 q = *(const uint2*)(smK + c * 256 + (((4 * ks + tig) ^ ((c & 3) << 2)) << 3));
                    bf[nt][0] = q.x; bf[nt][1] = q.y;
                }
#pragma unroll
                for (int m = 0; m < 2; m++)
#pragma unroll
                    for (int nt = 0; nt < 4; ++nt)
                        mma_f16(s[m][nt], af[m][0], af[m][1], af[m][2], af[m][3],
                                bf[nt][0], bf[nt][1]);
            }
        }
        __syncthreads();   // K reads done (smem region stable; P region separate anyway)

        if (!skip) {
            const float scale = 0.08838834764831845f;  // 1/sqrt(128)
            if (d == w) {
#pragma unroll
                for (int m = 0; m < 2; m++) {
                    int r1 = m * 16 + gid, r2 = r1 + 8;
#pragma unroll
                    for (int nt = 0; nt < 4; ++nt) {
                        int c0 = nt * 8 + tig * 2;
                        s[m][nt][0] = (c0     <= r1) ? s[m][nt][0] * scale : -1e30f;
                        s[m][nt][1] = (c0 + 1 <= r1) ? s[m][nt][1] * scale : -1e30f;
                        s[m][nt][2] = (c0     <= r2) ? s[m][nt][2] * scale : -1e30f;
                        s[m][nt][3] = (c0 + 1 <= r2) ? s[m][nt][3] * scale : -1e30f;
                    }
                }
            } else {
#pragma unroll
                for (int m = 0; m < 2; m++)
#pragma unroll
                    for (int nt = 0; nt < 4; ++nt) {
                        s[m][nt][0] *= scale; s[m][nt][1] *= scale;
                        s[m][nt][2] *= scale; s[m][nt][3] *= scale;
                    }
            }

#pragma unroll
            for (int m = 0; m < 2; m++) {
                float m1 = -1e30f, m2 = -1e30f;
#pragma unroll
                for (int nt = 0; nt < 4; ++nt) {
                    m1 = fmaxf(m1, fmaxf(s[m][nt][0], s[m][nt][1]));
                    m2 = fmaxf(m2, fmaxf(s[m][nt][2], s[m][nt][3]));
                }
                m1 = fmaxf(m1, __shfl_xor_sync(0xffffffffu, m1, 1));
                m1 = fmaxf(m1, __shfl_xor_sync(0xffffffffu, m1, 2));
                m2 = fmaxf(m2, __shfl_xor_sync(0xffffffffu, m2, 1));
                m2 = fmaxf(m2, __shfl_xor_sync(0xffffffffu, m2, 2));

                float nm1 = fmaxf(mx[m][0], m1), nm2 = fmaxf(mx[m][1], m2);
                float al1 = __expf(mx[m][0] - nm1), al2 = __expf(mx[m][1] - nm2);
                float sum1 = 0.f, sum2 = 0.f;
#pragma unroll
                for (int nt = 0; nt < 4; ++nt) {
                    s[m][nt][0] = __expf(s[m][nt][0] - nm1); sum1 += s[m][nt][0];
                    s[m][nt][1] = __expf(s[m][nt][1] - nm1); sum1 += s[m][nt][1];
                    s[m][nt][2] = __expf(s[m][nt][2] - nm2); sum2 += s[m][nt][2];
                    s[m][nt][3] = __expf(s[m][nt][3] - nm2); sum2 += s[m][nt][3];
                }
                sum1 += __shfl_xor_sync(0xffffffffu, sum1, 1);
                sum1 += __shfl_xor_sync(0xffffffffu, sum1, 2);
                sum2 += __shfl_xor_sync(0xffffffffu, sum2, 1);
                sum2 += __shfl_xor_sync(0xffffffffu, sum2, 2);

                ls[m][0] = ls[m][0] * al1 + sum1; mx[m][0] = nm1;
                ls[m][1] = ls[m][1] * al2 + sum2; mx[m][1] = nm2;
#pragma unroll
                for (int nt = 0; nt < 16; ++nt) {
                    o[m][nt][0] *= al1; o[m][nt][1] *= al1;
                    o[m][nt][2] *= al2; o[m][nt][3] *= al2;
                }

                // write P (fp16) — warp-private rows, stride 40 halfs
                int rA = wr + m * 16 + gid, rB = rA + 8;
#pragma unroll
                for (int nt = 0; nt < 4; ++nt) {
                    int c0 = nt * 8 + tig * 2;
                    *(__half2*)&Ps[rA * 40 + c0] = __floats2half2_rn(s[m][nt][0], s[m][nt][1]);
                    *(__half2*)&Ps[rB * 40 + c0] = __floats2half2_rn(s[m][nt][2], s[m][nt][3]);
                }
            }
            __syncwarp();

            // o += P @ V : k-dim 32 -> 2 k16 steps, 16 n-tiles (head cols)
#pragma unroll
            for (int ks = 0; ks < 2; ++ks) {
                uint32_t af[2][4];
#pragma unroll
                for (int m = 0; m < 2; m++) {
                    int r = wr + m * 16 + gid;
                    af[m][0] = *(const uint32_t*)&Ps[r * 40 + 16 * ks + 2 * tig];
                    af[m][1] = *(const uint32_t*)&Ps[(r + 8) * 40 + 16 * ks + 2 * tig];
                    af[m][2] = *(const uint32_t*)&Ps[r * 40 + 16 * ks + 2 * tig + 8];
                    af[m][3] = *(const uint32_t*)&Ps[(r + 8) * 40 + 16 * ks + 2 * tig + 8];
                }
#pragma unroll
                for (int nt = 0; nt < 16; ++nt) {
                    int n = nt * 8 + gid;
                    uint32_t b0 = *(const uint32_t*)&VTs[n * 40 + 16 * ks + 2 * tig];
                    uint32_t b1 = *(const uint32_t*)&VTs[n * 40 + 16 * ks + 2 * tig + 8];
#pragma unroll
                    for (int m = 0; m < 2; m++)
                        mma_f16(o[m][nt], af[m][0], af[m][1], af[m][2], af[m][3], b0, b1);
                }
            }
        }
    }

    // epilogue: fp16 + pair-permute along head dim for the O-GEMM A operand.
    // pair p = 4nt+tig -> grp = nt>>1, dst element = grp*16 + 4tig + 2(nt&1).
#pragma unroll
    for (int m = 0; m < 2; m++) {
        const float inv1 = 1.f / ls[m][0], inv2 = 1.f / ls[m][1];
        const int r1 = q0 + wr + m * 16 + gid;
#pragma unroll
        for (int nt = 0; nt < 16; ++nt) {
            int dst = h * HD + (nt >> 1) * 16 + 4 * tig + 2 * (nt & 1);
            *(__half2*)&g_attnh[(size_t)r1 * DIM + dst] =
                __floats2half2_rn(o[m][nt][0] * inv1, o[m][nt][1] * inv1);
            *(__half2*)&g_attnh[(size_t)(r1 + 8) * DIM + dst] =
                __floats2half2_rn(o[m][nt][2] * inv2, o[m][nt][3] * inv2);
        }
    }
}

// ---------------------------------------------------------------------------
extern "C" void kernel_launch(void* const* d_in, const int* in_sizes, int n_in,
                              void* d_out, int out_size) {
    (void)in_sizes; (void)n_in; (void)out_size;
    const float* x  = (const float*)d_in[0];
    const float* wq = (const float*)d_in[1];
    const float* wk = (const float*)d_in[2];
    const float* wv = (const float*)d_in[3];
    const float* wo = (const float*)d_in[4];
    float* out = (float*)d_out;

    float *q, *k;
    __half *qh, *kh, *attnh, *xh, *wqh, *wkh, *wvh, *woh;
    cudaGetSymbolAddress((void**)&q, g_q);
    cudaGetSymbolAddress((void**)&k, g_k);
    cudaGetSymbolAddress((void**)&qh, g_qh);
    cudaGetSymbolAddress((void**)&kh, g_kh);
    cudaGetSymbolAddress((void**)&attnh, g_attnh);
    cudaGetSymbolAddress((void**)&xh, g_xh);
    cudaGetSymbolAddress((void**)&wqh, g_wqh);
    cudaGetSymbolAddress((void**)&wkh, g_wkh);
    cudaGetSymbolAddress((void**)&wvh, g_wvh);
    cudaGetSymbolAddress((void**)&woh, g_woh);

    cudaFuncSetAttribute(gemm_qkv_kernel, cudaFuncAttributeMaxDynamicSharedMemorySize, GEMM_SMEM);
    cudaFuncSetAttribute(gemm_kernel, cudaFuncAttributeMaxDynamicSharedMemorySize, GEMM_SMEM);
    cudaFuncSetAttribute(attn_kernel, cudaFuncAttributeMaxDynamicSharedMemorySize, ATTN_SMEM);

    // fp16 + pair-permute prep of all GEMM operands (16-el groups)
    {
        const int T = 256;
        prep_kernel<<<(SEQ * DIM / 16 + T - 1) / T, T>>>(x, xh, SEQ * DIM / 16);
        prep_kernel<<<(DIM * DIM / 16 + T - 1) / T, T>>>(wq, wqh, DIM * DIM / 16);
        prep_kernel<<<(KVD * DIM / 16 + T - 1) / T, T>>>(wk, wkh, KVD * DIM / 16);
        prep_kernel<<<(KVD * DIM / 16 + T - 1) / T, T>>>(wv, wvh, KVD * DIM / 16);
        prep_kernel<<<(DIM * DIM / 16 + T - 1) / T, T>>>(wo, woh, DIM * DIM / 16);
    }

    // Merged Q/K/V projections (V written fp16-transposed)
    gemm_qkv_kernel<<<dim3(48, SEQ / 128), 128, GEMM_SMEM>>>();

    // RoPE: fp32 in -> fp16 pair-permuted out
    rope_kernel<<<(SEQ * NH * 64) / 256, 256>>>(q, qh, NH);
    rope_kernel<<<(SEQ * NKV * 64) / 256, 256>>>(k, kh, NKV);

    // Attention: 16 q-tiles x 32 heads, 3 CTAs/SM
    attn_kernel<<<dim3(SEQ / 128, NH), 128, ATTN_SMEM>>>();

    // Output projection straight into d_out (fp32 store)
    gemm_kernel<<<dim3(DIM / 128, SEQ / 128), 128, GEMM_SMEM>>>(attnh, woh, out, DIM, DIM);
}